// round 12
// baseline (speedup 1.0000x reference)
#include <cuda_runtime.h>
#include <cuda_fp16.h>
#include <cstdint>
#include <cstddef>

#define TT 2056
#define NTOK 520
#define HIDD 512
#define NHEAD 8
#define ADIM 64
#define FFD 2048

// ---------------- scratch (device globals; no allocation allowed) ----------
__device__ float  g_X  [TT*HIDD];
__device__ __half g_X16[TT*HIDD];
__device__ float  g_P  [4*TT*HIDD];       // split-K partials
__device__ __half g_Q16[TT*HIDD];
__device__ __half g_K16[TT*HIDD];
__device__ __half g_V16[TT*HIDD];
__device__ __half g_O16[TT*HIDD];
__device__ __half g_H16[TT*FFD];
__device__ float  g_PB [NHEAD*NTOK*NTOK];
__device__ __half g_WtQ [6*HIDD*HIDD];
__device__ __half g_WtK [6*HIDD*HIDD];
__device__ __half g_WtV [6*HIDD*HIDD];
__device__ __half g_WtO [6*HIDD*HIDD];
__device__ __half g_WtF1[6*HIDD*FFD];
__device__ __half g_WtF2[6*FFD*HIDD];

// ---------------- ptx helpers ----------------
__device__ __forceinline__ uint32_t h2_as_u32(__half2 v) {
    union { __half2 h; uint32_t u; } cvt;
    cvt.h = v;
    return cvt.u;
}
__device__ __forceinline__ void mma_f16(float* c, const uint32_t* a, uint32_t b0, uint32_t b1) {
    asm volatile("mma.sync.aligned.m16n8k16.row.col.f32.f16.f16.f32 "
        "{%0,%1,%2,%3}, {%4,%5,%6,%7}, {%8,%9}, {%0,%1,%2,%3};"
        : "+f"(c[0]), "+f"(c[1]), "+f"(c[2]), "+f"(c[3])
        : "r"(a[0]), "r"(a[1]), "r"(a[2]), "r"(a[3]), "r"(b0), "r"(b1));
}
__device__ __forceinline__ void ldmx4(uint32_t* r, uint32_t saddr) {
    asm volatile("ldmatrix.sync.aligned.m8n8.x4.shared.b16 {%0,%1,%2,%3}, [%4];"
        : "=r"(r[0]), "=r"(r[1]), "=r"(r[2]), "=r"(r[3]) : "r"(saddr));
}
__device__ __forceinline__ void ldmx4t(uint32_t* r, uint32_t saddr) {
    asm volatile("ldmatrix.sync.aligned.m8n8.x4.trans.shared.b16 {%0,%1,%2,%3}, [%4];"
        : "=r"(r[0]), "=r"(r[1]), "=r"(r[2]), "=r"(r[3]) : "r"(saddr));
}
__device__ __forceinline__ void cpasync16(uint32_t dst, const void* src, int srcsize) {
    asm volatile("cp.async.cg.shared.global [%0], [%1], 16, %2;"
                 :: "r"(dst), "l"(src), "r"(srcsize) : "memory");
}
__device__ __forceinline__ void cp_commit() {
    asm volatile("cp.async.commit_group;" ::: "memory");
}
template<int N>
__device__ __forceinline__ void cp_wait() {
    asm volatile("cp.async.wait_group %0;" :: "n"(N) : "memory");
}

__device__ __forceinline__ float blk_sum(float v, float* red) {
    int t = threadIdx.x;
    red[t] = v; __syncthreads();
    #pragma unroll
    for (int s = 128; s > 0; s >>= 1) {
        if (t < s) red[t] += red[t + s];
        __syncthreads();
    }
    float r = red[0];
    __syncthreads();
    return r;
}

// ---------------- weight transposes ----------------
__global__ void __launch_bounds__(256) transpose4_kernel(
    const float* __restrict__ Wq, const float* __restrict__ Wk,
    const float* __restrict__ Wv, const float* __restrict__ Wo,
    __half* __restrict__ WtQ, __half* __restrict__ WtK,
    __half* __restrict__ WtV, __half* __restrict__ WtO)
{
    __shared__ float tile[32][33];
    int w = blockIdx.z & 3, l = blockIdx.z >> 2;
    const float* src = ((w == 0) ? Wq : (w == 1) ? Wk : (w == 2) ? Wv : Wo)
                       + (size_t)l*HIDD*HIDD;
    __half* dst = ((w == 0) ? WtQ : (w == 1) ? WtK : (w == 2) ? WtV : WtO)
                  + (size_t)l*HIDD*HIDD;
    int tx = threadIdx.x & 31, ty = threadIdx.x >> 5;
    int nb = blockIdx.x * 32, kb = blockIdx.y * 32;
    #pragma unroll
    for (int i = 0; i < 32; i += 8)
        tile[ty + i][tx] = src[(size_t)(kb + ty + i) * HIDD + nb + tx];
    __syncthreads();
    #pragma unroll
    for (int i = 0; i < 32; i += 8)
        dst[(size_t)(nb + ty + i) * HIDD + kb + tx] = __float2half(tile[tx][ty + i]);
}

__global__ void __launch_bounds__(256) transpose_kernel(
    const float* __restrict__ src, __half* __restrict__ dst,
    int K, int N, long sstr, long dstr)
{
    __shared__ float tile[32][33];
    src += (long)blockIdx.z * sstr;
    dst += (long)blockIdx.z * dstr;
    int tx = threadIdx.x & 31, ty = threadIdx.x >> 5;
    int nb = blockIdx.x * 32, kb = blockIdx.y * 32;
    #pragma unroll
    for (int i = 0; i < 32; i += 8)
        tile[ty + i][tx] = src[(size_t)(kb + ty + i) * N + nb + tx];
    __syncthreads();
    #pragma unroll
    for (int i = 0; i < 32; i += 8)
        dst[(size_t)(nb + ty + i) * K + kb + tx] = __float2half(tile[tx][ty + i]);
}

// ---------------- positional bias ----------------
__global__ void __launch_bounds__(256) pb_kernel(
    const int* __restrict__ rpe_a, const int* __restrict__ rpe_d,
    const float* __restrict__ mask,
    const float* __restrict__ emb_a, const float* __restrict__ emb_d)
{
    int idx = blockIdx.x * 256 + threadIdx.x;
    if (idx >= NTOK*NTOK) return;
    int a = rpe_a[idx];
    int d = rpe_d[idx];
    float m = mask[idx];
    const float inv = 0.125f;
    #pragma unroll
    for (int h = 0; h < NHEAD; h++)
        g_PB[(size_t)h*NTOK*NTOK + idx] = (emb_a[a*NHEAD + h] + emb_d[d*NHEAD + h]) * inv + m;
}

// ---------------- embedding ----------------
__global__ void __launch_bounds__(256) embed_kernel(
    const float* __restrict__ obj, const float* __restrict__ st0,
    const float* __restrict__ Wpg, const float* __restrict__ bpg,
    const float* __restrict__ pgg, const float* __restrict__ pgb,
    const float* __restrict__ Wps, const float* __restrict__ bps,
    const float* __restrict__ psg, const float* __restrict__ psb)
{
    __shared__ float red[256];
    __shared__ float s_in[100];
    int row = blockIdx.x;
    int t = threadIdx.x;
    float v0, v1;
    if (row < 8) {
        if (t < 100) s_in[t] = obj[row*100 + t];
        __syncthreads();
        float a0 = bpg[t], a1 = bpg[t + 256];
        #pragma unroll 4
        for (int k = 0; k < 100; k++) {
            float x = s_in[k];
            a0 += x * Wpg[k*HIDD + t];
            a1 += x * Wpg[k*HIDD + t + 256];
        }
        v0 = a0; v1 = a1;
        __syncthreads();
    } else {
        int r = row - 8;
        int base = (r >> 2)*10 + (r & 3)*2;
        float a = st0[base], b = st0[base + 1];
        v0 = a*Wps[t]       + b*Wps[HIDD + t]       + bps[t];
        v1 = a*Wps[t + 256] + b*Wps[HIDD + t + 256] + bps[t + 256];
    }
    float mean = blk_sum(v0 + v1, red) * (1.0f/512.0f);
    float d0 = v0 - mean, d1 = v1 - mean;
    float var = blk_sum(d0*d0 + d1*d1, red) * (1.0f/512.0f);
    float rstd = rsqrtf(var + 1e-5f);
    const float* gg = (row < 8) ? pgg : psg;
    const float* gb = (row < 8) ? pgb : psb;
    float o0 = d0*rstd*gg[t] + gb[t];
    float o1 = d1*rstd*gg[t + 256] + gb[t + 256];
    o0 = (o0 >= 0.f) ? o0 : 0.01f*o0;
    o1 = (o1 >= 0.f) ? o1 : 0.01f*o1;
    g_X[(size_t)row*HIDD + t]         = o0;
    g_X[(size_t)row*HIDD + t + 256]   = o1;
    g_X16[(size_t)row*HIDD + t]       = __float2half(o0);
    g_X16[(size_t)row*HIDD + t + 256] = __float2half(o1);
}

// ---------------- sum(4 partials)+res+bias then LayerNorm -----------------
__global__ void __launch_bounds__(256) ln_sum_kernel(
    const float* __restrict__ p, const float* __restrict__ res,
    const float* __restrict__ bias,
    const float* __restrict__ g, const float* __restrict__ b,
    float* __restrict__ out, __half* __restrict__ out16)
{
    const size_t S = (size_t)TT*HIDD;
    int wid = threadIdx.x >> 5, lane = threadIdx.x & 31;
    int row = blockIdx.x * 8 + wid;
    if (row >= TT) return;
    size_t roff = (size_t)row*HIDD;
    float4 v[4];
    float s = 0.f;
    #pragma unroll
    for (int i = 0; i < 4; i++) {
        size_t e = roff + (lane + i*32)*4;
        float4 a0 = *(const float4*)&p[e];
        float4 a1 = *(const float4*)&p[S + e];
        float4 a2 = *(const float4*)&p[2*S + e];
        float4 a3 = *(const float4*)&p[3*S + e];
        float4 rv = *(const float4*)&res[e];
        float4 bv = *(const float4*)&bias[(lane + i*32)*4];
        v[i].x = a0.x + a1.x + a2.x + a3.x + rv.x + bv.x;
        v[i].y = a0.y + a1.y + a2.y + a3.y + rv.y + bv.y;
        v[i].z = a0.z + a1.z + a2.z + a3.z + rv.z + bv.z;
        v[i].w = a0.w + a1.w + a2.w + a3.w + rv.w + bv.w;
        s += (v[i].x + v[i].y) + (v[i].z + v[i].w);
    }
    #pragma unroll
    for (int o = 16; o > 0; o >>= 1) s += __shfl_xor_sync(0xffffffffu, s, o);
    float mean = s * (1.0f/512.0f);
    float q = 0.f;
    #pragma unroll
    for (int i = 0; i < 4; i++) {
        float dx = v[i].x - mean, dy = v[i].y - mean;
        float dz = v[i].z - mean, dw = v[i].w - mean;
        q += dx*dx + dy*dy + dz*dz + dw*dw;
    }
    #pragma unroll
    for (int o = 16; o > 0; o >>= 1) q += __shfl_xor_sync(0xffffffffu, q, o);
    float rstd = rsqrtf(q * (1.0f/512.0f) + 1e-5f);
    const float4* gp = (const float4*)g;
    const float4* bp = (const float4*)b;
    float4* op = (float4*)(out + roff);
    #pragma unroll
    for (int i = 0; i < 4; i++) {
        float4 gv = gp[lane + i*32];
        float4 bv = bp[lane + i*32];
        float4 o;
        o.x = (v[i].x - mean)*rstd*gv.x + bv.x;
        o.y = (v[i].y - mean)*rstd*gv.y + bv.y;
        o.z = (v[i].z - mean)*rstd*gv.z + bv.z;
        o.w = (v[i].w - mean)*rstd*gv.w + bv.w;
        op[lane + i*32] = o;
        if (out16) {
            uint2 pk;
            pk.x = h2_as_u32(__floats2half2_rn(o.x, o.y));
            pk.y = h2_as_u32(__floats2half2_rn(o.z, o.w));
            *(uint2*)&out16[roff + (lane + i*32)*4] = pk;
        }
    }
}

// ---------------- fp16 HMMA GEMM ----------------
// EPI: 0 none, 1 leaky-relu, 3 split-K partial (z = K-slice, f32, no bias).
#define APITCH 40
template<int EPI, bool OUT16>
__global__ void __launch_bounds__(256) tgemm_kernel(
    const __half* __restrict__ A,
    const __half* __restrict__ Bt0, const __half* __restrict__ Bt1, const __half* __restrict__ Bt2,
    const float* __restrict__ bias0, const float* __restrict__ bias1, const float* __restrict__ bias2,
    void* __restrict__ C0v, void* __restrict__ C1v, void* __restrict__ C2v,
    int M, int N, int K, int lda, int ldb)
{
    int z = blockIdx.z;
    const __half* Bt;
    const float* bias;
    void* Cv;
    if (EPI == 3) {
        A   += (size_t)z * K;
        Bt   = Bt0 + (size_t)z * K;
        bias = nullptr;
        Cv   = (float*)C0v + (size_t)z * ((size_t)TT*HIDD);
    } else {
        Bt   = (z == 0) ? Bt0   : (z == 1) ? Bt1   : Bt2;
        bias = (z == 0) ? bias0 : (z == 1) ? bias1 : bias2;
        Cv   = (z == 0) ? C0v   : (z == 1) ? C1v   : C2v;
    }

    __shared__ __align__(16) __half sA[2][128*APITCH];
    __shared__ __align__(16) __half sB[2][128*APITCH];

    int m0 = blockIdx.y * 128;
    int n0 = blockIdx.x * 128;
    int tid  = threadIdx.x;
    int lane = tid & 31, wid = tid >> 5;
    int wm = wid & 1;
    int wn = wid >> 1;

    uint32_t aB[2], bB[2];
    aB[0] = (uint32_t)__cvta_generic_to_shared(sA[0]);
    aB[1] = (uint32_t)__cvta_generic_to_shared(sA[1]);
    bB[0] = (uint32_t)__cvta_generic_to_shared(sB[0]);
    bB[1] = (uint32_t)__cvta_generic_to_shared(sB[1]);

    float acc[4][4][4];
    #pragma unroll
    for (int mt = 0; mt < 4; mt++)
        #pragma unroll
        for (int nt = 0; nt < 4; nt++)
            #pragma unroll
            for (int e = 0; e < 4; e++) acc[mt][nt][e] = 0.f;

    int NC = K >> 5;

    auto load_chunk = [&](int c) {
        int buf = c & 1;
        int k0 = c << 5;
        #pragma unroll
        for (int i = 0; i < 2; i++) {
            int u = tid*2 + i;
            int r = u >> 2;
            int q = u & 3;
            uint32_t doff = (uint32_t)(r*APITCH + q*8) * 2;
            int gr = m0 + r;
            int ok = (gr < M) ? 16 : 0;
            if (gr >= M) gr = 0;
            cpasync16(aB[buf] + doff, A  + (size_t)gr*lda + k0 + q*8, ok);
            cpasync16(bB[buf] + doff, Bt + (size_t)(n0 + r)*ldb + k0 + q*8, 16);
        }
        cp_commit();
    };

    load_chunk(0);

    int rA = lane & 15;
    int cA = (lane >> 4) * 8;

    for (int c = 0; c < NC; c++) {
        if (c + 1 < NC) { load_chunk(c + 1); cp_wait<1>(); }
        else            { cp_wait<0>(); }
        __syncthreads();

        int buf = c & 1;
        uint32_t ab = aB[buf], bb = bB[buf];
        #pragma unroll
        for (int kk = 0; kk < 32; kk += 16) {
            uint32_t af[4][4], bf[2][4];
            #pragma unroll
            for (int mt = 0; mt < 4; mt++)
                ldmx4(af[mt], ab + (uint32_t)((wm*64 + mt*16 + rA)*APITCH + kk + cA)*2);
            #pragma unroll
            for (int p = 0; p < 2; p++)
                ldmx4(bf[p], bb + (uint32_t)((wn*32 + p*16 + rA)*APITCH + kk + cA)*2);
            #pragma unroll
            for (int mt = 0; mt < 4; mt++)
                #pragma unroll
                for (int nt = 0; nt < 4; nt++)
                    mma_f16(acc[mt][nt], af[mt], bf[nt>>1][nt&1], bf[nt>>1][(nt&1)+2]);
        }
        __syncthreads();
    }

    int g  = lane >> 2;
    int t4 = lane & 3;
    #pragma unroll
    for (int mt = 0; mt < 4; mt++) {
        #pragma unroll
        for (int h = 0; h < 2; h++) {
            int row = m0 + wm*64 + mt*16 + g + h*8;
            if (row < M) {
                #pragma unroll
                for (int nt = 0; nt < 4; nt++) {
                    int col = n0 + wn*32 + nt*8 + 2*t4;
                    float x = acc[mt][nt][h*2 + 0];
                    float y = acc[mt][nt][h*2 + 1];
                    if (EPI != 3) { x += bias[col]; y += bias[col + 1]; }
                    if (EPI == 1) {
                        x = (x >= 0.f) ? x : 0.01f*x;
                        y = (y >= 0.f) ? y : 0.01f*y;
                    }
                    if (OUT16) {
                        __half2 o = __floats2half2_rn(x, y);
                        *(__half2*)((__half*)Cv + (size_t)row*N + col) = o;
                    } else {
                        float2 o; o.x = x; o.y = y;
                        *(float2*)((float*)Cv + (size_t)row*N + col) = o;
                    }
                }
            }
        }
    }
}

// ---------------- HMMA flash attention: BQ=64, 4 warps, no split ----------
// CTA = (64-query tile, head), 128 threads = 4 warps x 16 q-rows.
// Full key loop (33 tiles of 64), double-buffered K/V, direct O16 write.
#define BQ 64
#define BK 64
#define QP 72    // halfs per smem row (144B, conflict-free ldmatrix)
#define NKT 33
#define ATTN_SMEM ((64*QP + 4*64*QP) * 2)   // Q + 2 K-bufs + 2 V-bufs = 45KB

__device__ __forceinline__ int expand_map(int i) {
    return (i < 8) ? i : 8 + ((i - 8) >> 2);
}

__global__ void __launch_bounds__(128, 2) attn_kernel(
    const __half* __restrict__ Q, const __half* __restrict__ K,
    const __half* __restrict__ V, __half* __restrict__ O16)
{
    extern __shared__ __half sm16[];
    __half* sQ = sm16;
    __half* sK = sQ + 64*QP;
    __half* sV = sK + 2*64*QP;

    int h  = blockIdx.y;
    int q0 = blockIdx.x * BQ;
    int tid = threadIdx.x;
    int lane = tid & 31, wid = tid >> 5;   // wid 0..3
    int g = lane >> 2, t4 = lane & 3;
    int rA = lane & 15, cA = (lane >> 4) * 8;

    uint32_t sQu = (uint32_t)__cvta_generic_to_shared(sQ);
    uint32_t sKu = (uint32_t)__cvta_generic_to_shared(sK);
    uint32_t sVu = (uint32_t)__cvta_generic_to_shared(sV);

    // load Q tile: 64 rows x 64 halfs = 512 16B chunks, 128 threads x 4
    #pragma unroll
    for (int i = 0; i < 4; i++) {
        int u = tid*4 + i;
        int r = u >> 3, q = u & 7;
        int qi = q0 + r;
        int ok = (qi < TT) ? 16 : 0;
        if (qi >= TT) qi = 0;
        cpasync16(sQu + (uint32_t)(r*QP + q*8)*2, Q + (size_t)qi*HIDD + h*ADIM + q*8, ok);
    }
    cp_commit();

    auto loadKV = [&](int c) {
        int b = c & 1;
        int k0 = c * BK;
        #pragma unroll
        for (int i = 0; i < 4; i++) {
            int u = tid*4 + i;
            int r = u >> 3, q = u & 7;
            int kj = k0 + r;
            int ok = (kj < TT) ? 16 : 0;
            if (kj >= TT) kj = 0;
            uint32_t doff = (uint32_t)(b*64*QP + r*QP + q*8)*2;
            cpasync16(sKu + doff, K + (size_t)kj*HIDD + h*ADIM + q*8, ok);
            cpasync16(sVu + doff, V + (size_t)kj*HIDD + h*ADIM + q*8, ok);
        }
        cp_commit();
    };

    loadKV(0);
    cp_wait<1>();     // Q group complete
    __syncthreads();

    // preload Q fragments (4 dim-ksteps)
    uint32_t qf[4][4];
    #pragma unroll
    for (int ks = 0; ks < 4; ks++)
        ldmx4(qf[ks], sQu + (uint32_t)((wid*16 + rA)*QP + ks*16 + cA)*2);

    int qi_g  = q0 + wid*16 + g;
    int qi_g8 = qi_g + 8;
    const float* pb0 = g_PB + ((size_t)h*NTOK + expand_map(qi_g  < TT ? qi_g  : 0))*NTOK;
    const float* pb1 = g_PB + ((size_t)h*NTOK + expand_map(qi_g8 < TT ? qi_g8 : 0))*NTOK;

    float mrun0 = -1e30f, mrun1 = -1e30f;
    float l0 = 0.f, l1 = 0.f;
    float of[8][4];
    #pragma unroll
    for (int nt = 0; nt < 8; nt++)
        #pragma unroll
        for (int e = 0; e < 4; e++) of[nt][e] = 0.f;

    for (int c = 0; c < NKT; c++) {
        if (c + 1 < NKT) { loadKV(c + 1); cp_wait<1>(); }
        else             { cp_wait<0>(); }
        __syncthreads();

        int b = c & 1;
        int k0 = c * BK;
        uint32_t kb = sKu + (uint32_t)(b*64*QP)*2;
        uint32_t vb = sVu + (uint32_t)(b*64*QP)*2;

        // S = Q @ K^T : 8 n-tiles (keys) x 4 k-steps (dims)
        float sc[8][4];
        #pragma unroll
        for (int nt = 0; nt < 8; nt++)
            #pragma unroll
            for (int e = 0; e < 4; e++) sc[nt][e] = 0.f;
        #pragma unroll
        for (int ks = 0; ks < 4; ks++) {
            #pragma unroll
            for (int kr = 0; kr < 4; kr++) {
                uint32_t kf[4];
                ldmx4(kf, kb + (uint32_t)((kr*16 + rA)*QP + ks*16 + cA)*2);
                mma_f16(sc[2*kr],     qf[ks], kf[0], kf[2]);
                mma_f16(sc[2*kr + 1], qf[ks], kf[1], kf[3]);
            }
        }

        // scale + bias (+ key padding)
        const float inv = 0.125f;
        #pragma unroll
        for (int nt = 0; nt < 8; nt++) {
            int kj0 = k0 + nt*8 + 2*t4;
            if (kj0 < TT) {
                int oj = expand_map(kj0);
                sc[nt][0] = sc[nt][0]*inv + pb0[oj];
                sc[nt][2] = sc[nt][2]*inv + pb1[oj];
            } else { sc[nt][0] = -1e30f; sc[nt][2] = -1e30f; }
            int kj1 = kj0 + 1;
            if (kj1 < TT) {
                int oj = expand_map(kj1);
                sc[nt][1] = sc[nt][1]*inv + pb0[oj];
                sc[nt][3] = sc[nt][3]*inv + pb1[oj];
            } else { sc[nt][1] = -1e30f; sc[nt][3] = -1e30f; }
        }

        // online softmax (rows g and g+8; quad reduction over t4 lanes)
        float m0 = -1e30f, m1 = -1e30f;
        #pragma unroll
        for (int nt = 0; nt < 8; nt++) {
            m0 = fmaxf(m0, fmaxf(sc[nt][0], sc[nt][1]));
            m1 = fmaxf(m1, fmaxf(sc[nt][2], sc[nt][3]));
        }
        m0 = fmaxf(m0, __shfl_xor_sync(0xffffffffu, m0, 1));
        m0 = fmaxf(m0, __shfl_xor_sync(0xffffffffu, m0, 2));
        m1 = fmaxf(m1, __shfl_xor_sync(0xffffffffu, m1, 1));
        m1 = fmaxf(m1, __shfl_xor_sync(0xffffffffu, m1, 2));
        float mn0 = fmaxf(mrun0, m0), mn1 = fmaxf(mrun1, m1);
        float c0 = __expf(mrun0 - mn0), c1 = __expf(mrun1 - mn1);
        mrun0 = mn0; mrun1 = mn1;

        float ls0 = 0.f, ls1 = 0.f;
        uint32_t pa[4][4];
        #pragma unroll
        for (int nt = 0; nt < 8; nt++) {
            float p0 = __expf(sc[nt][0] - mn0);
            float p1 = __expf(sc[nt][1] - mn0);
            float p2 = __expf(sc[nt][2] - mn1);
            float p3 = __expf(sc[nt][3] - mn1);
            ls0 += p0 + p1; ls1 += p2 + p3;
            uint32_t h01 = h2_as_u32(__floats2half2_rn(p0, p1));
            uint32_t h23 = h2_as_u32(__floats2half2_rn(p2, p3));
            int s = nt >> 1;
            if ((nt & 1) == 0) { pa[s][0] = h01; pa[s][1] = h23; }
            else               { pa[s][2] = h01; pa[s][3] = h23; }
        }
        ls0 += __shfl_xor_sync(0xffffffffu, ls0, 1);
        ls0 += __shfl_xor_sync(0xffffffffu, ls0, 2);
        ls1 += __shfl_xor_sync(0xffffffffu, ls1, 1);
        ls1 += __shfl_xor_sync(0xffffffffu, ls1, 2);
        l0 = l0*c0 + ls0;
        l1 = l1*c1 + ls1;

        #pragma unroll
        for (int nt = 0; nt < 8; nt++) {
            of[nt][0] *= c0; of[nt][1] *= c0;
            of[nt][2] *= c1; of[nt][3] *= c1;
        }

        // O += P @ V : 4 key-steps x 8 dim-ntiles (V via ldmatrix.trans)
        int vrow = ((lane >> 3) & 1)*8 + (lane & 7);
        int vcol = (lane >> 4)*8;
        #pragma unroll
        for (int s = 0; s < 4; s++) {
            #pragma unroll
            for (int dn = 0; dn < 4; dn++) {
                uint32_t vf[4];
                ldmx4t(vf, vb + (uint32_t)((s*16 + vrow)*QP + dn*16 + vcol)*2);
                mma_f16(of[2*dn],     pa[s], vf[0], vf[1]);
                mma_f16(of[2*dn + 1], pa[s], vf[2], vf[3]);
            }
        }
        __syncthreads();
    }

    float invl0 = 1.0f / l0, invl1 = 1.0f / l1;
    #pragma unroll
    for (int nt = 0; nt < 8; nt++) {
        int d = nt*8 + 2*t4;
        if (qi_g < TT)
            *(__half2*)&O16[(size_t)qi_g*HIDD + h*ADIM + d] =
                __floats2half2_rn(of[nt][0]*invl0, of[nt][1]*invl0);
        if (qi_g8 < TT)
            *(__half2*)&O16[(size_t)qi_g8*HIDD + h*ADIM + d] =
                __floats2half2_rn(of[nt][2]*invl1, of[nt][3]*invl1);
    }
}

// ---------------- launch ----------------
extern "C" void kernel_launch(void* const* d_in, const int* in_sizes, int n_in,
                              void* d_out, int out_size)
{
    const float* obj   = (const float*)d_in[0];
    const float* st0   = (const float*)d_in[2];
    const int*   rpe_a = (const int*)  d_in[3];
    const int*   rpe_d = (const int*)  d_in[4];
    const float* mask  = (const float*)d_in[5];
    const float* Wpg   = (const float*)d_in[6];
    const float* bpg   = (const float*)d_in[7];
    const float* pgg   = (const float*)d_in[8];
    const float* pgb   = (const float*)d_in[9];
    const float* Wps   = (const float*)d_in[10];
    const float* bps   = (const float*)d_in[11];
    const float* psg   = (const float*)d_in[12];
    const float* psb   = (const float*)d_in[13];
    const float* emb_a = (const float*)d_in[14];
    const float* emb_d = (const float*)d_in[15];
    const float* Wq    = (const float*)d_in[16];
    const float* bq    = (const float*)d_in[17];
    const float* Wk    = (const float*)d_in[18];
    const float* bk    = (const float*)d_in[19];
    const float* Wv    = (const float*)d_in[20];
    const float* bv    = (const float*)d_in[21];
    const float* Wo    = (const float*)d_in[22];
    const float* bo    = (const float*)d_in[23];
    const float* W1    = (const float*)d_in[24];
    const float* b1    = (const float*)d_in[25];
    const float* W2    = (const float*)d_in[26];
    const float* b2    = (const float*)d_in[27];
    const float* ln1g  = (const float*)d_in[28];
    const float* ln1b  = (const float*)d_in[29];
    const float* ln2g  = (const float*)d_in[30];
    const float* ln2b  = (const float*)d_in[31];
    float* out = (float*)d_out;

    float *X, *P;
    __half *X16, *Q16, *K16, *V16, *O16, *H16;
    __half *WtQ, *WtK, *WtV, *WtO, *WtF1, *WtF2;
    cudaGetSymbolAddress((void**)&X,    g_X);
    cudaGetSymbolAddress((void**)&X16,  g_X16);
    cudaGetSymbolAddress((void**)&P,    g_P);
    cudaGetSymbolAddress((void**)&Q16,  g_Q16);
    cudaGetSymbolAddress((void**)&K16,  g_K16);
    cudaGetSymbolAddress((void**)&V16,  g_V16);
    cudaGetSymbolAddress((void**)&O16,  g_O16);
    cudaGetSymbolAddress((void**)&H16,  g_H16);
    cudaGetSymbolAddress((void**)&WtQ,  g_WtQ);
    cudaGetSymbolAddress((void**)&WtK,  g_WtK);
    cudaGetSymbolAddress((void**)&WtV,  g_WtV);
    cudaGetSymbolAddress((void**)&WtO,  g_WtO);
    cudaGetSymbolAddress((void**)&WtF1, g_WtF1);
    cudaGetSymbolAddress((void**)&WtF2, g_WtF2);

    cudaFuncSetAttribute(attn_kernel, cudaFuncAttributeMaxDynamicSharedMemorySize, ATTN_SMEM);

    transpose4_kernel<<<dim3(16,16,24), 256>>>(Wq, Wk, Wv, Wo, WtQ, WtK, WtV, WtO);
    transpose_kernel<<<dim3(64,16,6), 256>>>(W1, WtF1, HIDD, FFD, (long)HIDD*FFD, (long)FFD*HIDD);
    transpose_kernel<<<dim3(16,64,6), 256>>>(W2, WtF2, FFD, HIDD, (long)FFD*HIDD, (long)HIDD*FFD);

    pb_kernel<<<(NTOK*NTOK + 255)/256, 256>>>(rpe_a, rpe_d, mask, emb_a, emb_d);
    embed_kernel<<<TT, 256>>>(obj, st0, Wpg, bpg, pgg, pgb, Wps, bps, psg, psb);

    for (int l = 0; l < 6; l++) {
        const __half* WtQl  = WtQ  + (size_t)l*HIDD*HIDD;
        const __half* WtKl  = WtK  + (size_t)l*HIDD*HIDD;
        const __half* WtVl  = WtV  + (size_t)l*HIDD*HIDD;
        const __half* WtOl  = WtO  + (size_t)l*HIDD*HIDD;
        const __half* WtF1l = WtF1 + (size_t)l*HIDD*FFD;
        const __half* WtF2l = WtF2 + (size_t)l*FFD*HIDD;
        const float* bql = bq + (size_t)l*HIDD;
        const float* bkl = bk + (size_t)l*HIDD;
        const float* bvl = bv + (size_t)l*HIDD;
        const float* bol = bo + (size_t)l*HIDD;
        const float* b1l = b1 + (size_t)l*FFD;
        const float* b2l = b2 + (size_t)l*HIDD;

        // fused QKV -> fp16
        tgemm_kernel<0, true><<<dim3(4, 17, 3), 256>>>(
            X16, WtQl, WtKl, WtVl, bql, bkl, bvl, Q16, K16, V16,
            TT, HIDD, HIDD, HIDD, HIDD);

        attn_kernel<<<dim3(33, NHEAD), 128, ATTN_SMEM>>>(Q16, K16, V16, O16);

        // O-proj split-K x4 -> 4 partials in g_P
        tgemm_kernel<3, false><<<dim3(4, 17, 4), 256>>>(
            O16, WtOl, WtOl, WtOl, nullptr, nullptr, nullptr, P, P, P,
            TT, HIDD, HIDD/4, HIDD, HIDD);
        // sum partials + residual(X) + bias, LN1 -> X, X16
        ln_sum_kernel<<<257, 256>>>(P, X, bol, ln1g + l*HIDD, ln1b + l*HIDD, X, X16);

        // FF1 -> H16
        tgemm_kernel<1, true><<<dim3(16, 17, 1), 256>>>(
            X16, WtF1l, WtF1l, WtF1l, b1l, b1l, b1l, H16, H16, H16,
            TT, FFD, HIDD, HIDD, HIDD);

        // FF2 split-K x4 -> 4 partials in g_P
        tgemm_kernel<3, false><<<dim3(4, 17, 4), 256>>>(
            H16, WtF2l, WtF2l, WtF2l, nullptr, nullptr, nullptr, P, P, P,
            TT, HIDD, FFD/4, FFD, FFD);
        // sum partials + residual(X) + bias, LN2 -> (out|X), X16
        ln_sum_kernel<<<257, 256>>>(P, X, b2l, ln2g + l*HIDD, ln2b + l*HIDD,
                                    (l == 5) ? out : X, (l == 5) ? nullptr : X16);
    }
}

// round 13
// speedup vs baseline: 1.1280x; 1.1280x over previous
#include <cuda_runtime.h>
#include <cuda_fp16.h>
#include <cstdint>
#include <cstddef>

#define TT 2056
#define NTOK 520
#define HIDD 512
#define NHEAD 8
#define ADIM 64
#define FFD 2048

// ---------------- scratch (device globals; no allocation allowed) ----------
__device__ float  g_X  [TT*HIDD];
__device__ __half g_X16[TT*HIDD];
__device__ float  g_P  [4*TT*HIDD];       // split-K partials
__device__ __half g_Q16[TT*HIDD];
__device__ __half g_K16[TT*HIDD];
__device__ __half g_V16[TT*HIDD];
__device__ __half g_O16[TT*HIDD];
__device__ __half g_H16[TT*FFD];
__device__ float  g_PB [NHEAD*NTOK*NTOK];
__device__ float  g_OP [2][TT*HIDD];      // attn split partials (unnormalized)
__device__ float2 g_ML [2][TT*NHEAD];     // attn split (max, sum)
__device__ __half g_WtQ [6*HIDD*HIDD];
__device__ __half g_WtK [6*HIDD*HIDD];
__device__ __half g_WtV [6*HIDD*HIDD];
__device__ __half g_WtO [6*HIDD*HIDD];
__device__ __half g_WtF1[6*HIDD*FFD];
__device__ __half g_WtF2[6*FFD*HIDD];

// ---------------- ptx helpers ----------------
__device__ __forceinline__ uint32_t h2_as_u32(__half2 v) {
    union { __half2 h; uint32_t u; } cvt;
    cvt.h = v;
    return cvt.u;
}
__device__ __forceinline__ void mma_f16(float* c, const uint32_t* a, uint32_t b0, uint32_t b1) {
    asm volatile("mma.sync.aligned.m16n8k16.row.col.f32.f16.f16.f32 "
        "{%0,%1,%2,%3}, {%4,%5,%6,%7}, {%8,%9}, {%0,%1,%2,%3};"
        : "+f"(c[0]), "+f"(c[1]), "+f"(c[2]), "+f"(c[3])
        : "r"(a[0]), "r"(a[1]), "r"(a[2]), "r"(a[3]), "r"(b0), "r"(b1));
}
__device__ __forceinline__ void ldmx4(uint32_t* r, uint32_t saddr) {
    asm volatile("ldmatrix.sync.aligned.m8n8.x4.shared.b16 {%0,%1,%2,%3}, [%4];"
        : "=r"(r[0]), "=r"(r[1]), "=r"(r[2]), "=r"(r[3]) : "r"(saddr));
}
__device__ __forceinline__ void ldmx4t(uint32_t* r, uint32_t saddr) {
    asm volatile("ldmatrix.sync.aligned.m8n8.x4.trans.shared.b16 {%0,%1,%2,%3}, [%4];"
        : "=r"(r[0]), "=r"(r[1]), "=r"(r[2]), "=r"(r[3]) : "r"(saddr));
}
__device__ __forceinline__ void cpasync16(uint32_t dst, const void* src, int srcsize) {
    asm volatile("cp.async.cg.shared.global [%0], [%1], 16, %2;"
                 :: "r"(dst), "l"(src), "r"(srcsize) : "memory");
}
__device__ __forceinline__ void cp_commit() {
    asm volatile("cp.async.commit_group;" ::: "memory");
}
template<int N>
__device__ __forceinline__ void cp_wait() {
    asm volatile("cp.async.wait_group %0;" :: "n"(N) : "memory");
}

__device__ __forceinline__ float blk_sum(float v, float* red) {
    int t = threadIdx.x;
    red[t] = v; __syncthreads();
    #pragma unroll
    for (int s = 128; s > 0; s >>= 1) {
        if (t < s) red[t] += red[t + s];
        __syncthreads();
    }
    float r = red[0];
    __syncthreads();
    return r;
}

// ---------------- weight transposes ----------------
__global__ void __launch_bounds__(256) transpose4_kernel(
    const float* __restrict__ Wq, const float* __restrict__ Wk,
    const float* __restrict__ Wv, const float* __restrict__ Wo,
    __half* __restrict__ WtQ, __half* __restrict__ WtK,
    __half* __restrict__ WtV, __half* __restrict__ WtO)
{
    __shared__ float tile[32][33];
    int w = blockIdx.z & 3, l = blockIdx.z >> 2;
    const float* src = ((w == 0) ? Wq : (w == 1) ? Wk : (w == 2) ? Wv : Wo)
                       + (size_t)l*HIDD*HIDD;
    __half* dst = ((w == 0) ? WtQ : (w == 1) ? WtK : (w == 2) ? WtV : WtO)
                  + (size_t)l*HIDD*HIDD;
    int tx = threadIdx.x & 31, ty = threadIdx.x >> 5;
    int nb = blockIdx.x * 32, kb = blockIdx.y * 32;
    #pragma unroll
    for (int i = 0; i < 32; i += 8)
        tile[ty + i][tx] = src[(size_t)(kb + ty + i) * HIDD + nb + tx];
    __syncthreads();
    #pragma unroll
    for (int i = 0; i < 32; i += 8)
        dst[(size_t)(nb + ty + i) * HIDD + kb + tx] = __float2half(tile[tx][ty + i]);
}

__global__ void __launch_bounds__(256) transpose_kernel(
    const float* __restrict__ src, __half* __restrict__ dst,
    int K, int N, long sstr, long dstr)
{
    __shared__ float tile[32][33];
    src += (long)blockIdx.z * sstr;
    dst += (long)blockIdx.z * dstr;
    int tx = threadIdx.x & 31, ty = threadIdx.x >> 5;
    int nb = blockIdx.x * 32, kb = blockIdx.y * 32;
    #pragma unroll
    for (int i = 0; i < 32; i += 8)
        tile[ty + i][tx] = src[(size_t)(kb + ty + i) * N + nb + tx];
    __syncthreads();
    #pragma unroll
    for (int i = 0; i < 32; i += 8)
        dst[(size_t)(nb + ty + i) * K + kb + tx] = __float2half(tile[tx][ty + i]);
}

// ---------------- positional bias ----------------
__global__ void __launch_bounds__(256) pb_kernel(
    const int* __restrict__ rpe_a, const int* __restrict__ rpe_d,
    const float* __restrict__ mask,
    const float* __restrict__ emb_a, const float* __restrict__ emb_d)
{
    int idx = blockIdx.x * 256 + threadIdx.x;
    if (idx >= NTOK*NTOK) return;
    int a = rpe_a[idx];
    int d = rpe_d[idx];
    float m = mask[idx];
    const float inv = 0.125f;
    #pragma unroll
    for (int h = 0; h < NHEAD; h++)
        g_PB[(size_t)h*NTOK*NTOK + idx] = (emb_a[a*NHEAD + h] + emb_d[d*NHEAD + h]) * inv + m;
}

// ---------------- embedding ----------------
__global__ void __launch_bounds__(256) embed_kernel(
    const float* __restrict__ obj, const float* __restrict__ st0,
    const float* __restrict__ Wpg, const float* __restrict__ bpg,
    const float* __restrict__ pgg, const float* __restrict__ pgb,
    const float* __restrict__ Wps, const float* __restrict__ bps,
    const float* __restrict__ psg, const float* __restrict__ psb)
{
    __shared__ float red[256];
    __shared__ float s_in[100];
    int row = blockIdx.x;
    int t = threadIdx.x;
    float v0, v1;
    if (row < 8) {
        if (t < 100) s_in[t] = obj[row*100 + t];
        __syncthreads();
        float a0 = bpg[t], a1 = bpg[t + 256];
        #pragma unroll 4
        for (int k = 0; k < 100; k++) {
            float x = s_in[k];
            a0 += x * Wpg[k*HIDD + t];
            a1 += x * Wpg[k*HIDD + t + 256];
        }
        v0 = a0; v1 = a1;
        __syncthreads();
    } else {
        int r = row - 8;
        int base = (r >> 2)*10 + (r & 3)*2;
        float a = st0[base], b = st0[base + 1];
        v0 = a*Wps[t]       + b*Wps[HIDD + t]       + bps[t];
        v1 = a*Wps[t + 256] + b*Wps[HIDD + t + 256] + bps[t + 256];
    }
    float mean = blk_sum(v0 + v1, red) * (1.0f/512.0f);
    float d0 = v0 - mean, d1 = v1 - mean;
    float var = blk_sum(d0*d0 + d1*d1, red) * (1.0f/512.0f);
    float rstd = rsqrtf(var + 1e-5f);
    const float* gg = (row < 8) ? pgg : psg;
    const float* gb = (row < 8) ? pgb : psb;
    float o0 = d0*rstd*gg[t] + gb[t];
    float o1 = d1*rstd*gg[t + 256] + gb[t + 256];
    o0 = (o0 >= 0.f) ? o0 : 0.01f*o0;
    o1 = (o1 >= 0.f) ? o1 : 0.01f*o1;
    g_X[(size_t)row*HIDD + t]         = o0;
    g_X[(size_t)row*HIDD + t + 256]   = o1;
    g_X16[(size_t)row*HIDD + t]       = __float2half(o0);
    g_X16[(size_t)row*HIDD + t + 256] = __float2half(o1);
}

// ---------------- sum(NP partials)+res+bias then LayerNorm -----------------
template<int NP>
__global__ void __launch_bounds__(256) ln_sum_kernel(
    const float* __restrict__ p, const float* __restrict__ res,
    const float* __restrict__ bias,
    const float* __restrict__ g, const float* __restrict__ b,
    float* __restrict__ out, __half* __restrict__ out16)
{
    const size_t S = (size_t)TT*HIDD;
    int wid = threadIdx.x >> 5, lane = threadIdx.x & 31;
    int row = blockIdx.x * 8 + wid;
    if (row >= TT) return;
    size_t roff = (size_t)row*HIDD;
    float4 v[4];
    float s = 0.f;
    #pragma unroll
    for (int i = 0; i < 4; i++) {
        size_t e = roff + (lane + i*32)*4;
        float4 acc = *(const float4*)&p[e];
        #pragma unroll
        for (int np = 1; np < NP; np++) {
            float4 a = *(const float4*)&p[(size_t)np*S + e];
            acc.x += a.x; acc.y += a.y; acc.z += a.z; acc.w += a.w;
        }
        float4 rv = *(const float4*)&res[e];
        float4 bv = *(const float4*)&bias[(lane + i*32)*4];
        v[i].x = acc.x + rv.x + bv.x;
        v[i].y = acc.y + rv.y + bv.y;
        v[i].z = acc.z + rv.z + bv.z;
        v[i].w = acc.w + rv.w + bv.w;
        s += (v[i].x + v[i].y) + (v[i].z + v[i].w);
    }
    #pragma unroll
    for (int o = 16; o > 0; o >>= 1) s += __shfl_xor_sync(0xffffffffu, s, o);
    float mean = s * (1.0f/512.0f);
    float q = 0.f;
    #pragma unroll
    for (int i = 0; i < 4; i++) {
        float dx = v[i].x - mean, dy = v[i].y - mean;
        float dz = v[i].z - mean, dw = v[i].w - mean;
        q += dx*dx + dy*dy + dz*dz + dw*dw;
    }
    #pragma unroll
    for (int o = 16; o > 0; o >>= 1) q += __shfl_xor_sync(0xffffffffu, q, o);
    float rstd = rsqrtf(q * (1.0f/512.0f) + 1e-5f);
    const float4* gp = (const float4*)g;
    const float4* bp = (const float4*)b;
    float4* op = (float4*)(out + roff);
    #pragma unroll
    for (int i = 0; i < 4; i++) {
        float4 gv = gp[lane + i*32];
        float4 bv = bp[lane + i*32];
        float4 o;
        o.x = (v[i].x - mean)*rstd*gv.x + bv.x;
        o.y = (v[i].y - mean)*rstd*gv.y + bv.y;
        o.z = (v[i].z - mean)*rstd*gv.z + bv.z;
        o.w = (v[i].w - mean)*rstd*gv.w + bv.w;
        op[lane + i*32] = o;
        if (out16) {
            uint2 pk;
            pk.x = h2_as_u32(__floats2half2_rn(o.x, o.y));
            pk.y = h2_as_u32(__floats2half2_rn(o.z, o.w));
            *(uint2*)&out16[roff + (lane + i*32)*4] = pk;
        }
    }
}

// ---------------- fp16 HMMA GEMM ----------------
// EPI: 0 none (z==0 output scaled by 0.125 for folded attention scale),
//      1 leaky-relu, 3 split-K partial (z = K-slice, f32, no bias).
#define APITCH 40
template<int EPI, bool OUT16>
__global__ void __launch_bounds__(256) tgemm_kernel(
    const __half* __restrict__ A,
    const __half* __restrict__ Bt0, const __half* __restrict__ Bt1, const __half* __restrict__ Bt2,
    const float* __restrict__ bias0, const float* __restrict__ bias1, const float* __restrict__ bias2,
    void* __restrict__ C0v, void* __restrict__ C1v, void* __restrict__ C2v,
    int M, int N, int K, int lda, int ldb)
{
    int z = blockIdx.z;
    const __half* Bt;
    const float* bias;
    void* Cv;
    if (EPI == 3) {
        A   += (size_t)z * K;
        Bt   = Bt0 + (size_t)z * K;
        bias = nullptr;
        Cv   = (float*)C0v + (size_t)z * ((size_t)TT*HIDD);
    } else {
        Bt   = (z == 0) ? Bt0   : (z == 1) ? Bt1   : Bt2;
        bias = (z == 0) ? bias0 : (z == 1) ? bias1 : bias2;
        Cv   = (z == 0) ? C0v   : (z == 1) ? C1v   : C2v;
    }

    __shared__ __align__(16) __half sA[2][128*APITCH];
    __shared__ __align__(16) __half sB[2][128*APITCH];

    int m0 = blockIdx.y * 128;
    int n0 = blockIdx.x * 128;
    int tid  = threadIdx.x;
    int lane = tid & 31, wid = tid >> 5;
    int wm = wid & 1;
    int wn = wid >> 1;

    uint32_t aB[2], bB[2];
    aB[0] = (uint32_t)__cvta_generic_to_shared(sA[0]);
    aB[1] = (uint32_t)__cvta_generic_to_shared(sA[1]);
    bB[0] = (uint32_t)__cvta_generic_to_shared(sB[0]);
    bB[1] = (uint32_t)__cvta_generic_to_shared(sB[1]);

    float acc[4][4][4];
    #pragma unroll
    for (int mt = 0; mt < 4; mt++)
        #pragma unroll
        for (int nt = 0; nt < 4; nt++)
            #pragma unroll
            for (int e = 0; e < 4; e++) acc[mt][nt][e] = 0.f;

    int NC = K >> 5;

    auto load_chunk = [&](int c) {
        int buf = c & 1;
        int k0 = c << 5;
        #pragma unroll
        for (int i = 0; i < 2; i++) {
            int u = tid*2 + i;
            int r = u >> 2;
            int q = u & 3;
            uint32_t doff = (uint32_t)(r*APITCH + q*8) * 2;
            int gr = m0 + r;
            int ok = (gr < M) ? 16 : 0;
            if (gr >= M) gr = 0;
            cpasync16(aB[buf] + doff, A  + (size_t)gr*lda + k0 + q*8, ok);
            cpasync16(bB[buf] + doff, Bt + (size_t)(n0 + r)*ldb + k0 + q*8, 16);
        }
        cp_commit();
    };

    load_chunk(0);

    int rA = lane & 15;
    int cA = (lane >> 4) * 8;

    for (int c = 0; c < NC; c++) {
        if (c + 1 < NC) { load_chunk(c + 1); cp_wait<1>(); }
        else            { cp_wait<0>(); }
        __syncthreads();

        int buf = c & 1;
        uint32_t ab = aB[buf], bb = bB[buf];
        #pragma unroll
        for (int kk = 0; kk < 32; kk += 16) {
            uint32_t af[4][4], bf[2][4];
            #pragma unroll
            for (int mt = 0; mt < 4; mt++)
                ldmx4(af[mt], ab + (uint32_t)((wm*64 + mt*16 + rA)*APITCH + kk + cA)*2);
            #pragma unroll
            for (int p = 0; p < 2; p++)
                ldmx4(bf[p], bb + (uint32_t)((wn*32 + p*16 + rA)*APITCH + kk + cA)*2);
            #pragma unroll
            for (int mt = 0; mt < 4; mt++)
                #pragma unroll
                for (int nt = 0; nt < 4; nt++)
                    mma_f16(acc[mt][nt], af[mt], bf[nt>>1][nt&1], bf[nt>>1][(nt&1)+2]);
        }
        __syncthreads();
    }

    float oscale = (EPI == 0 && z == 0) ? 0.125f : 1.0f;
    int g  = lane >> 2;
    int t4 = lane & 3;
    #pragma unroll
    for (int mt = 0; mt < 4; mt++) {
        #pragma unroll
        for (int h = 0; h < 2; h++) {
            int row = m0 + wm*64 + mt*16 + g + h*8;
            if (row < M) {
                #pragma unroll
                for (int nt = 0; nt < 4; nt++) {
                    int col = n0 + wn*32 + nt*8 + 2*t4;
                    float x = acc[mt][nt][h*2 + 0];
                    float y = acc[mt][nt][h*2 + 1];
                    if (EPI != 3) { x += bias[col]; y += bias[col + 1]; }
                    if (EPI == 0) { x *= oscale; y *= oscale; }
                    if (EPI == 1) {
                        x = (x >= 0.f) ? x : 0.01f*x;
                        y = (y >= 0.f) ? y : 0.01f*y;
                    }
                    if (OUT16) {
                        __half2 o = __floats2half2_rn(x, y);
                        *(__half2*)((__half*)Cv + (size_t)row*N + col) = o;
                    } else {
                        float2 o; o.x = x; o.y = y;
                        *(float2*)((float*)Cv + (size_t)row*N + col) = o;
                    }
                }
            }
        }
    }
}

// ---------------- HMMA flash attention, split-K x2 (round-11 proven) -------
// Q pre-scaled by 0.125 in QKV epilogue; pb already carries pos*inv + mask.
#define BQ 128
#define BK 64
#define QP 72
#define NKT 33
#define ATTN_SMEM ((128*QP + 4*64*QP) * 2)

__device__ __forceinline__ int expand_map(int i) {
    return (i < 8) ? i : 8 + ((i - 8) >> 2);
}

__global__ void __launch_bounds__(256, 2) attn_kernel(
    const __half* __restrict__ Q, const __half* __restrict__ K,
    const __half* __restrict__ V)
{
    extern __shared__ __half sm16[];
    __half* sQ = sm16;
    __half* sK = sQ + 128*QP;
    __half* sV = sK + 2*64*QP;

    int h  = blockIdx.y;
    int q0 = blockIdx.x * BQ;
    int split = blockIdx.z;
    int ntiles = (NKT + 1 - split) >> 1;
    int tid = threadIdx.x;
    int lane = tid & 31, wid = tid >> 5;
    int g = lane >> 2, t4 = lane & 3;
    int rA = lane & 15, cA = (lane >> 4) * 8;

    uint32_t sQu = (uint32_t)__cvta_generic_to_shared(sQ);
    uint32_t sKu = (uint32_t)__cvta_generic_to_shared(sK);
    uint32_t sVu = (uint32_t)__cvta_generic_to_shared(sV);

    #pragma unroll
    for (int i = 0; i < 4; i++) {
        int u = tid*4 + i;
        int r = u >> 3, q = u & 7;
        int qi = q0 + r;
        int ok = (qi < TT) ? 16 : 0;
        if (qi >= TT) qi = 0;
        cpasync16(sQu + (uint32_t)(r*QP + q*8)*2, Q + (size_t)qi*HIDD + h*ADIM + q*8, ok);
    }
    cp_commit();

    auto loadKV = [&](int c) {
        int b = c & 1;
        int k0 = (split + 2*c) * BK;
        #pragma unroll
        for (int i = 0; i < 2; i++) {
            int u = tid*2 + i;
            int r = u >> 3, q = u & 7;
            int kj = k0 + r;
            int ok = (kj < TT) ? 16 : 0;
            if (kj >= TT) kj = 0;
            uint32_t doff = (uint32_t)(b*64*QP + r*QP + q*8)*2;
            cpasync16(sKu + doff, K + (size_t)kj*HIDD + h*ADIM + q*8, ok);
            cpasync16(sVu + doff, V + (size_t)kj*HIDD + h*ADIM + q*8, ok);
        }
        cp_commit();
    };

    loadKV(0);
    cp_wait<1>();
    __syncthreads();

    uint32_t qf[4][4];
    #pragma unroll
    for (int ks = 0; ks < 4; ks++)
        ldmx4(qf[ks], sQu + (uint32_t)((wid*16 + rA)*QP + ks*16 + cA)*2);

    int qi_g  = q0 + wid*16 + g;
    int qi_g8 = qi_g + 8;
    const float* pb0 = g_PB + ((size_t)h*NTOK + expand_map(qi_g  < TT ? qi_g  : 0))*NTOK;
    const float* pb1 = g_PB + ((size_t)h*NTOK + expand_map(qi_g8 < TT ? qi_g8 : 0))*NTOK;

    float mrun0 = -1e30f, mrun1 = -1e30f;
    float l0 = 0.f, l1 = 0.f;
    float of[8][4];
    #pragma unroll
    for (int nt = 0; nt < 8; nt++)
        #pragma unroll
        for (int e = 0; e < 4; e++) of[nt][e] = 0.f;

    for (int c = 0; c < ntiles; c++) {
        if (c + 1 < ntiles) { loadKV(c + 1); cp_wait<1>(); }
        else                { cp_wait<0>(); }
        __syncthreads();

        int b = c & 1;
        int k0 = (split + 2*c) * BK;
        uint32_t kb = sKu + (uint32_t)(b*64*QP)*2;
        uint32_t vb = sVu + (uint32_t)(b*64*QP)*2;

        float sc[8][4];
        #pragma unroll
        for (int nt = 0; nt < 8; nt++)
            #pragma unroll
            for (int e = 0; e < 4; e++) sc[nt][e] = 0.f;
        #pragma unroll
        for (int ks = 0; ks < 4; ks++) {
            #pragma unroll
            for (int kr = 0; kr < 4; kr++) {
                uint32_t kf[4];
                ldmx4(kf, kb + (uint32_t)((kr*16 + rA)*QP + ks*16 + cA)*2);
                mma_f16(sc[2*kr],     qf[ks], kf[0], kf[2]);
                mma_f16(sc[2*kr + 1], qf[ks], kf[1], kf[3]);
            }
        }

        // bias + mask (Q already scaled by 0.125)
        #pragma unroll
        for (int nt = 0; nt < 8; nt++) {
            int kj0 = k0 + nt*8 + 2*t4;
            if (kj0 < TT) {
                int oj = expand_map(kj0);
                sc[nt][0] += pb0[oj];
                sc[nt][2] += pb1[oj];
            } else { sc[nt][0] = -1e30f; sc[nt][2] = -1e30f; }
            int kj1 = kj0 + 1;
            if (kj1 < TT) {
                int oj = expand_map(kj1);
                sc[nt][1] += pb0[oj];
                sc[nt][3] += pb1[oj];
            } else { sc[nt][1] = -1e30f; sc[nt][3] = -1e30f; }
        }

        float m0 = -1e30f, m1 = -1e30f;
        #pragma unroll
        for (int nt = 0; nt < 8; nt++) {
            m0 = fmaxf(m0, fmaxf(sc[nt][0], sc[nt][1]));
            m1 = fmaxf(m1, fmaxf(sc[nt][2], sc[nt][3]));
        }
        m0 = fmaxf(m0, __shfl_xor_sync(0xffffffffu, m0, 1));
        m0 = fmaxf(m0, __shfl_xor_sync(0xffffffffu, m0, 2));
        m1 = fmaxf(m1, __shfl_xor_sync(0xffffffffu, m1, 1));
        m1 = fmaxf(m1, __shfl_xor_sync(0xffffffffu, m1, 2));
        float mn0 = fmaxf(mrun0, m0), mn1 = fmaxf(mrun1, m1);
        float c0 = __expf(mrun0 - mn0), c1 = __expf(mrun1 - mn1);
        mrun0 = mn0; mrun1 = mn1;

        float ls0 = 0.f, ls1 = 0.f;
        uint32_t pa[4][4];
        #pragma unroll
        for (int nt = 0; nt < 8; nt++) {
            float p0 = __expf(sc[nt][0] - mn0);
            float p1 = __expf(sc[nt][1] - mn0);
            float p2 = __expf(sc[nt][2] - mn1);
            float p3 = __expf(sc[nt][3] - mn1);
            ls0 += p0 + p1; ls1 += p2 + p3;
            uint32_t h01 = h2_as_u32(__floats2half2_rn(p0, p1));
            uint32_t h23 = h2_as_u32(__floats2half2_rn(p2, p3));
            int s = nt >> 1;
            if ((nt & 1) == 0) { pa[s][0] = h01; pa[s][1] = h23; }
            else               { pa[s][2] = h01; pa[s][3] = h23; }
        }
        ls0 += __shfl_xor_sync(0xffffffffu, ls0, 1);
        ls0 += __shfl_xor_sync(0xffffffffu, ls0, 2);
        ls1 += __shfl_xor_sync(0xffffffffu, ls1, 1);
        ls1 += __shfl_xor_sync(0xffffffffu, ls1, 2);
        l0 = l0*c0 + ls0;
        l1 = l1*c1 + ls1;

        #pragma unroll
        for (int nt = 0; nt < 8; nt++) {
            of[nt][0] *= c0; of[nt][1] *= c0;
            of[nt][2] *= c1; of[nt][3] *= c1;
        }

        int vrow = ((lane >> 3) & 1)*8 + (lane & 7);
        int vcol = (lane >> 4)*8;
        #pragma unroll
        for (int s = 0; s < 4; s++) {
            #pragma unroll
            for (int dn = 0; dn < 4; dn++) {
                uint32_t vf[4];
                ldmx4t(vf, vb + (uint32_t)((s*16 + vrow)*QP + dn*16 + vcol)*2);
                mma_f16(of[2*dn],     pa[s], vf[0], vf[1]);
                mma_f16(of[2*dn + 1], pa[s], vf[2], vf[3]);
            }
        }
        __syncthreads();
    }

    #pragma unroll
    for (int nt = 0; nt < 8; nt++) {
        int d = nt*8 + 2*t4;
        if (qi_g < TT) {
            float2 o; o.x = of[nt][0]; o.y = of[nt][1];
            *(float2*)&g_OP[split][(size_t)qi_g*HIDD + h*ADIM + d] = o;
        }
        if (qi_g8 < TT) {
            float2 o; o.x = of[nt][2]; o.y = of[nt][3];
            *(float2*)&g_OP[split][(size_t)qi_g8*HIDD + h*ADIM + d] = o;
        }
    }
    if (t4 == 0) {
        if (qi_g  < TT) { float2 ml; ml.x = mrun0; ml.y = l0; g_ML[split][(size_t)qi_g*NHEAD  + h] = ml; }
        if (qi_g8 < TT) { float2 ml; ml.x = mrun1; ml.y = l1; g_ML[split][(size_t)qi_g8*NHEAD + h] = ml; }
    }
}

// ---------------- combine the two attention splits ----------------
__global__ void __launch_bounds__(256) attn_combine_kernel(__half* __restrict__ O16)
{
    int row = blockIdx.x;
    int t = threadIdx.x;
    #pragma unroll
    for (int p = 0; p < 2; p++) {
        int e = t + p*256;
        int h = e >> 6;
        float2 ml0 = g_ML[0][(size_t)row*NHEAD + h];
        float2 ml1 = g_ML[1][(size_t)row*NHEAD + h];
        float m = fmaxf(ml0.x, ml1.x);
        float w0 = __expf(ml0.x - m), w1 = __expf(ml1.x - m);
        float denom = ml0.y*w0 + ml1.y*w1;
        float o = (g_OP[0][(size_t)row*HIDD + e]*w0 + g_OP[1][(size_t)row*HIDD + e]*w1) / denom;
        O16[(size_t)row*HIDD + e] = __float2half(o);
    }
}

// ---------------- launch ----------------
extern "C" void kernel_launch(void* const* d_in, const int* in_sizes, int n_in,
                              void* d_out, int out_size)
{
    const float* obj   = (const float*)d_in[0];
    const float* st0   = (const float*)d_in[2];
    const int*   rpe_a = (const int*)  d_in[3];
    const int*   rpe_d = (const int*)  d_in[4];
    const float* mask  = (const float*)d_in[5];
    const float* Wpg   = (const float*)d_in[6];
    const float* bpg   = (const float*)d_in[7];
    const float* pgg   = (const float*)d_in[8];
    const float* pgb   = (const float*)d_in[9];
    const float* Wps   = (const float*)d_in[10];
    const float* bps   = (const float*)d_in[11];
    const float* psg   = (const float*)d_in[12];
    const float* psb   = (const float*)d_in[13];
    const float* emb_a = (const float*)d_in[14];
    const float* emb_d = (const float*)d_in[15];
    const float* Wq    = (const float*)d_in[16];
    const float* bq    = (const float*)d_in[17];
    const float* Wk    = (const float*)d_in[18];
    const float* bk    = (const float*)d_in[19];
    const float* Wv    = (const float*)d_in[20];
    const float* bv    = (const float*)d_in[21];
    const float* Wo    = (const float*)d_in[22];
    const float* bo    = (const float*)d_in[23];
    const float* W1    = (const float*)d_in[24];
    const float* b1    = (const float*)d_in[25];
    const float* W2    = (const float*)d_in[26];
    const float* b2    = (const float*)d_in[27];
    const float* ln1g  = (const float*)d_in[28];
    const float* ln1b  = (const float*)d_in[29];
    const float* ln2g  = (const float*)d_in[30];
    const float* ln2b  = (const float*)d_in[31];
    float* out = (float*)d_out;

    float *X, *P;
    __half *X16, *Q16, *K16, *V16, *O16, *H16;
    __half *WtQ, *WtK, *WtV, *WtO, *WtF1, *WtF2;
    cudaGetSymbolAddress((void**)&X,    g_X);
    cudaGetSymbolAddress((void**)&X16,  g_X16);
    cudaGetSymbolAddress((void**)&P,    g_P);
    cudaGetSymbolAddress((void**)&Q16,  g_Q16);
    cudaGetSymbolAddress((void**)&K16,  g_K16);
    cudaGetSymbolAddress((void**)&V16,  g_V16);
    cudaGetSymbolAddress((void**)&O16,  g_O16);
    cudaGetSymbolAddress((void**)&H16,  g_H16);
    cudaGetSymbolAddress((void**)&WtQ,  g_WtQ);
    cudaGetSymbolAddress((void**)&WtK,  g_WtK);
    cudaGetSymbolAddress((void**)&WtV,  g_WtV);
    cudaGetSymbolAddress((void**)&WtO,  g_WtO);
    cudaGetSymbolAddress((void**)&WtF1, g_WtF1);
    cudaGetSymbolAddress((void**)&WtF2, g_WtF2);

    cudaFuncSetAttribute(attn_kernel, cudaFuncAttributeMaxDynamicSharedMemorySize, ATTN_SMEM);

    transpose4_kernel<<<dim3(16,16,24), 256>>>(Wq, Wk, Wv, Wo, WtQ, WtK, WtV, WtO);
    transpose_kernel<<<dim3(64,16,6), 256>>>(W1, WtF1, HIDD, FFD, (long)HIDD*FFD, (long)FFD*HIDD);
    transpose_kernel<<<dim3(16,64,6), 256>>>(W2, WtF2, FFD, HIDD, (long)FFD*HIDD, (long)HIDD*FFD);

    pb_kernel<<<(NTOK*NTOK + 255)/256, 256>>>(rpe_a, rpe_d, mask, emb_a, emb_d);
    embed_kernel<<<TT, 256>>>(obj, st0, Wpg, bpg, pgg, pgb, Wps, bps, psg, psb);

    for (int l = 0; l < 6; l++) {
        const __half* WtQl  = WtQ  + (size_t)l*HIDD*HIDD;
        const __half* WtKl  = WtK  + (size_t)l*HIDD*HIDD;
        const __half* WtVl  = WtV  + (size_t)l*HIDD*HIDD;
        const __half* WtOl  = WtO  + (size_t)l*HIDD*HIDD;
        const __half* WtF1l = WtF1 + (size_t)l*HIDD*FFD;
        const __half* WtF2l = WtF2 + (size_t)l*FFD*HIDD;
        const float* bql = bq + (size_t)l*HIDD;
        const float* bkl = bk + (size_t)l*HIDD;
        const float* bvl = bv + (size_t)l*HIDD;
        const float* bol = bo + (size_t)l*HIDD;
        const float* b1l = b1 + (size_t)l*FFD;
        const float* b2l = b2 + (size_t)l*HIDD;

        // fused QKV -> fp16 (Q pre-scaled by 0.125 in epilogue)
        tgemm_kernel<0, true><<<dim3(4, 17, 3), 256>>>(
            X16, WtQl, WtKl, WtVl, bql, bkl, bvl, Q16, K16, V16,
            TT, HIDD, HIDD, HIDD, HIDD);

        attn_kernel<<<dim3(17, NHEAD, 2), 256, ATTN_SMEM>>>(Q16, K16, V16);
        attn_combine_kernel<<<TT, 256>>>(O16);

        // O-proj split-K x2 -> 2 partials in g_P
        tgemm_kernel<3, false><<<dim3(4, 17, 2), 256>>>(
            O16, WtOl, WtOl, WtOl, nullptr, nullptr, nullptr, P, P, P,
            TT, HIDD, HIDD/2, HIDD, HIDD);
        ln_sum_kernel<2><<<257, 256>>>(P, X, bol, ln1g + l*HIDD, ln1b + l*HIDD, X, X16);

        // FF1 -> H16
        tgemm_kernel<1, true><<<dim3(16, 17, 1), 256>>>(
            X16, WtF1l, WtF1l, WtF1l, b1l, b1l, b1l, H16, H16, H16,
            TT, FFD, HIDD, HIDD, HIDD);

        // FF2 split-K x4 -> 4 partials in g_P
        tgemm_kernel<3, false><<<dim3(4, 17, 4), 256>>>(
            H16, WtF2l, WtF2l, WtF2l, nullptr, nullptr, nullptr, P, P, P,
            TT, HIDD, FFD/4, FFD, FFD);
        ln_sum_kernel<4><<<257, 256>>>(P, X, b2l, ln2g + l*HIDD, ln2b + l*HIDD,
                                       (l == 5) ? out : X, (l == 5) ? nullptr : X16);
    }
}

// round 14
// speedup vs baseline: 1.1581x; 1.0266x over previous
#include <cuda_runtime.h>
#include <cuda_fp16.h>
#include <cstdint>
#include <cstddef>

#define TT 2056
#define NTOK 520
#define HIDD 512
#define NHEAD 8
#define ADIM 64
#define FFD 2048

// ---------------- scratch (device globals; no allocation allowed) ----------
__device__ float  g_X  [TT*HIDD];
__device__ __half g_X16[TT*HIDD];
__device__ float  g_P  [4*TT*HIDD];       // split-K partials
__device__ __half g_Q16[TT*HIDD];
__device__ __half g_K16[TT*HIDD];
__device__ __half g_V16[TT*HIDD];
__device__ __half g_O16[TT*HIDD];
__device__ __half g_H16[TT*FFD];
__device__ float  g_PB [NHEAD*NTOK*NTOK];
__device__ float  g_OP [2][TT*HIDD];      // attn split partials (unnormalized)
__device__ float2 g_ML [2][TT*NHEAD];     // attn split (max, sum)
__device__ __half g_WtQ [6*HIDD*HIDD];
__device__ __half g_WtK [6*HIDD*HIDD];
__device__ __half g_WtV [6*HIDD*HIDD];
__device__ __half g_WtO [6*HIDD*HIDD];
__device__ __half g_WtF1[6*HIDD*FFD];
__device__ __half g_WtF2[6*FFD*HIDD];

// ---------------- ptx helpers ----------------
__device__ __forceinline__ uint32_t h2_as_u32(__half2 v) {
    union { __half2 h; uint32_t u; } cvt;
    cvt.h = v;
    return cvt.u;
}
__device__ __forceinline__ void mma_f16(float* c, const uint32_t* a, uint32_t b0, uint32_t b1) {
    asm volatile("mma.sync.aligned.m16n8k16.row.col.f32.f16.f16.f32 "
        "{%0,%1,%2,%3}, {%4,%5,%6,%7}, {%8,%9}, {%0,%1,%2,%3};"
        : "+f"(c[0]), "+f"(c[1]), "+f"(c[2]), "+f"(c[3])
        : "r"(a[0]), "r"(a[1]), "r"(a[2]), "r"(a[3]), "r"(b0), "r"(b1));
}
__device__ __forceinline__ void ldmx4(uint32_t* r, uint32_t saddr) {
    asm volatile("ldmatrix.sync.aligned.m8n8.x4.shared.b16 {%0,%1,%2,%3}, [%4];"
        : "=r"(r[0]), "=r"(r[1]), "=r"(r[2]), "=r"(r[3]) : "r"(saddr));
}
__device__ __forceinline__ void ldmx4t(uint32_t* r, uint32_t saddr) {
    asm volatile("ldmatrix.sync.aligned.m8n8.x4.trans.shared.b16 {%0,%1,%2,%3}, [%4];"
        : "=r"(r[0]), "=r"(r[1]), "=r"(r[2]), "=r"(r[3]) : "r"(saddr));
}
__device__ __forceinline__ void cpasync16(uint32_t dst, const void* src, int srcsize) {
    asm volatile("cp.async.cg.shared.global [%0], [%1], 16, %2;"
                 :: "r"(dst), "l"(src), "r"(srcsize) : "memory");
}
__device__ __forceinline__ void cp_commit() {
    asm volatile("cp.async.commit_group;" ::: "memory");
}
template<int N>
__device__ __forceinline__ void cp_wait() {
    asm volatile("cp.async.wait_group %0;" :: "n"(N) : "memory");
}

__device__ __forceinline__ float blk_sum(float v, float* red) {
    int t = threadIdx.x;
    red[t] = v; __syncthreads();
    #pragma unroll
    for (int s = 128; s > 0; s >>= 1) {
        if (t < s) red[t] += red[t + s];
        __syncthreads();
    }
    float r = red[0];
    __syncthreads();
    return r;
}

// ---------------- weight transposes ----------------
__global__ void __launch_bounds__(256) transpose4_kernel(
    const float* __restrict__ Wq, const float* __restrict__ Wk,
    const float* __restrict__ Wv, const float* __restrict__ Wo,
    __half* __restrict__ WtQ, __half* __restrict__ WtK,
    __half* __restrict__ WtV, __half* __restrict__ WtO)
{
    __shared__ float tile[32][33];
    int w = blockIdx.z & 3, l = blockIdx.z >> 2;
    const float* src = ((w == 0) ? Wq : (w == 1) ? Wk : (w == 2) ? Wv : Wo)
                       + (size_t)l*HIDD*HIDD;
    __half* dst = ((w == 0) ? WtQ : (w == 1) ? WtK : (w == 2) ? WtV : WtO)
                  + (size_t)l*HIDD*HIDD;
    int tx = threadIdx.x & 31, ty = threadIdx.x >> 5;
    int nb = blockIdx.x * 32, kb = blockIdx.y * 32;
    #pragma unroll
    for (int i = 0; i < 32; i += 8)
        tile[ty + i][tx] = src[(size_t)(kb + ty + i) * HIDD + nb + tx];
    __syncthreads();
    #pragma unroll
    for (int i = 0; i < 32; i += 8)
        dst[(size_t)(nb + ty + i) * HIDD + kb + tx] = __float2half(tile[tx][ty + i]);
}

__global__ void __launch_bounds__(256) transpose_kernel(
    const float* __restrict__ src, __half* __restrict__ dst,
    int K, int N, long sstr, long dstr)
{
    __shared__ float tile[32][33];
    src += (long)blockIdx.z * sstr;
    dst += (long)blockIdx.z * dstr;
    int tx = threadIdx.x & 31, ty = threadIdx.x >> 5;
    int nb = blockIdx.x * 32, kb = blockIdx.y * 32;
    #pragma unroll
    for (int i = 0; i < 32; i += 8)
        tile[ty + i][tx] = src[(size_t)(kb + ty + i) * N + nb + tx];
    __syncthreads();
    #pragma unroll
    for (int i = 0; i < 32; i += 8)
        dst[(size_t)(nb + ty + i) * K + kb + tx] = __float2half(tile[tx][ty + i]);
}

// ---------------- positional bias ----------------
__global__ void __launch_bounds__(256) pb_kernel(
    const int* __restrict__ rpe_a, const int* __restrict__ rpe_d,
    const float* __restrict__ mask,
    const float* __restrict__ emb_a, const float* __restrict__ emb_d)
{
    int idx = blockIdx.x * 256 + threadIdx.x;
    if (idx >= NTOK*NTOK) return;
    int a = rpe_a[idx];
    int d = rpe_d[idx];
    float m = mask[idx];
    const float inv = 0.125f;
    #pragma unroll
    for (int h = 0; h < NHEAD; h++)
        g_PB[(size_t)h*NTOK*NTOK + idx] = (emb_a[a*NHEAD + h] + emb_d[d*NHEAD + h]) * inv + m;
}

// ---------------- embedding ----------------
__global__ void __launch_bounds__(256) embed_kernel(
    const float* __restrict__ obj, const float* __restrict__ st0,
    const float* __restrict__ Wpg, const float* __restrict__ bpg,
    const float* __restrict__ pgg, const float* __restrict__ pgb,
    const float* __restrict__ Wps, const float* __restrict__ bps,
    const float* __restrict__ psg, const float* __restrict__ psb)
{
    __shared__ float red[256];
    __shared__ float s_in[100];
    int row = blockIdx.x;
    int t = threadIdx.x;
    float v0, v1;
    if (row < 8) {
        if (t < 100) s_in[t] = obj[row*100 + t];
        __syncthreads();
        float a0 = bpg[t], a1 = bpg[t + 256];
        #pragma unroll 4
        for (int k = 0; k < 100; k++) {
            float x = s_in[k];
            a0 += x * Wpg[k*HIDD + t];
            a1 += x * Wpg[k*HIDD + t + 256];
        }
        v0 = a0; v1 = a1;
        __syncthreads();
    } else {
        int r = row - 8;
        int base = (r >> 2)*10 + (r & 3)*2;
        float a = st0[base], b = st0[base + 1];
        v0 = a*Wps[t]       + b*Wps[HIDD + t]       + bps[t];
        v1 = a*Wps[t + 256] + b*Wps[HIDD + t + 256] + bps[t + 256];
    }
    float mean = blk_sum(v0 + v1, red) * (1.0f/512.0f);
    float d0 = v0 - mean, d1 = v1 - mean;
    float var = blk_sum(d0*d0 + d1*d1, red) * (1.0f/512.0f);
    float rstd = rsqrtf(var + 1e-5f);
    const float* gg = (row < 8) ? pgg : psg;
    const float* gb = (row < 8) ? pgb : psb;
    float o0 = d0*rstd*gg[t] + gb[t];
    float o1 = d1*rstd*gg[t + 256] + gb[t + 256];
    o0 = (o0 >= 0.f) ? o0 : 0.01f*o0;
    o1 = (o1 >= 0.f) ? o1 : 0.01f*o1;
    g_X[(size_t)row*HIDD + t]         = o0;
    g_X[(size_t)row*HIDD + t + 256]   = o1;
    g_X16[(size_t)row*HIDD + t]       = __float2half(o0);
    g_X16[(size_t)row*HIDD + t + 256] = __float2half(o1);
}

// ---------------- sum(NP partials)+res+bias then LayerNorm -----------------
template<int NP>
__global__ void __launch_bounds__(256) ln_sum_kernel(
    const float* __restrict__ p, const float* __restrict__ res,
    const float* __restrict__ bias,
    const float* __restrict__ g, const float* __restrict__ b,
    float* __restrict__ out, __half* __restrict__ out16)
{
    const size_t S = (size_t)TT*HIDD;
    int wid = threadIdx.x >> 5, lane = threadIdx.x & 31;
    int row = blockIdx.x * 8 + wid;
    if (row >= TT) return;
    size_t roff = (size_t)row*HIDD;
    float4 v[4];
    float s = 0.f;
    #pragma unroll
    for (int i = 0; i < 4; i++) {
        size_t e = roff + (lane + i*32)*4;
        float4 acc = *(const float4*)&p[e];
        #pragma unroll
        for (int np = 1; np < NP; np++) {
            float4 a = *(const float4*)&p[(size_t)np*S + e];
            acc.x += a.x; acc.y += a.y; acc.z += a.z; acc.w += a.w;
        }
        float4 rv = *(const float4*)&res[e];
        float4 bv = *(const float4*)&bias[(lane + i*32)*4];
        v[i].x = acc.x + rv.x + bv.x;
        v[i].y = acc.y + rv.y + bv.y;
        v[i].z = acc.z + rv.z + bv.z;
        v[i].w = acc.w + rv.w + bv.w;
        s += (v[i].x + v[i].y) + (v[i].z + v[i].w);
    }
    #pragma unroll
    for (int o = 16; o > 0; o >>= 1) s += __shfl_xor_sync(0xffffffffu, s, o);
    float mean = s * (1.0f/512.0f);
    float q = 0.f;
    #pragma unroll
    for (int i = 0; i < 4; i++) {
        float dx = v[i].x - mean, dy = v[i].y - mean;
        float dz = v[i].z - mean, dw = v[i].w - mean;
        q += dx*dx + dy*dy + dz*dz + dw*dw;
    }
    #pragma unroll
    for (int o = 16; o > 0; o >>= 1) q += __shfl_xor_sync(0xffffffffu, q, o);
    float rstd = rsqrtf(q * (1.0f/512.0f) + 1e-5f);
    const float4* gp = (const float4*)g;
    const float4* bp = (const float4*)b;
    float4* op = (float4*)(out + roff);
    #pragma unroll
    for (int i = 0; i < 4; i++) {
        float4 gv = gp[lane + i*32];
        float4 bv = bp[lane + i*32];
        float4 o;
        o.x = (v[i].x - mean)*rstd*gv.x + bv.x;
        o.y = (v[i].y - mean)*rstd*gv.y + bv.y;
        o.z = (v[i].z - mean)*rstd*gv.z + bv.z;
        o.w = (v[i].w - mean)*rstd*gv.w + bv.w;
        op[lane + i*32] = o;
        if (out16) {
            uint2 pk;
            pk.x = h2_as_u32(__floats2half2_rn(o.x, o.y));
            pk.y = h2_as_u32(__floats2half2_rn(o.z, o.w));
            *(uint2*)&out16[roff + (lane + i*32)*4] = pk;
        }
    }
}

// ---------------- fp16 HMMA GEMM ----------------
// EPI: 0 none (z==0 output scaled by 0.125 for folded attention scale),
//      1 leaky-relu, 3 split-K partial (z = K-slice, f32, no bias).
#define APITCH 40
template<int EPI, bool OUT16>
__global__ void __launch_bounds__(256) tgemm_kernel(
    const __half* __restrict__ A,
    const __half* __restrict__ Bt0, const __half* __restrict__ Bt1, const __half* __restrict__ Bt2,
    const float* __restrict__ bias0, const float* __restrict__ bias1, const float* __restrict__ bias2,
    void* __restrict__ C0v, void* __restrict__ C1v, void* __restrict__ C2v,
    int M, int N, int K, int lda, int ldb)
{
    int z = blockIdx.z;
    const __half* Bt;
    const float* bias;
    void* Cv;
    if (EPI == 3) {
        A   += (size_t)z * K;
        Bt   = Bt0 + (size_t)z * K;
        bias = nullptr;
        Cv   = (float*)C0v + (size_t)z * ((size_t)TT*HIDD);
    } else {
        Bt   = (z == 0) ? Bt0   : (z == 1) ? Bt1   : Bt2;
        bias = (z == 0) ? bias0 : (z == 1) ? bias1 : bias2;
        Cv   = (z == 0) ? C0v   : (z == 1) ? C1v   : C2v;
    }

    __shared__ __align__(16) __half sA[2][128*APITCH];
    __shared__ __align__(16) __half sB[2][128*APITCH];

    int m0 = blockIdx.y * 128;
    int n0 = blockIdx.x * 128;
    int tid  = threadIdx.x;
    int lane = tid & 31, wid = tid >> 5;
    int wm = wid & 1;
    int wn = wid >> 1;

    uint32_t aB[2], bB[2];
    aB[0] = (uint32_t)__cvta_generic_to_shared(sA[0]);
    aB[1] = (uint32_t)__cvta_generic_to_shared(sA[1]);
    bB[0] = (uint32_t)__cvta_generic_to_shared(sB[0]);
    bB[1] = (uint32_t)__cvta_generic_to_shared(sB[1]);

    float acc[4][4][4];
    #pragma unroll
    for (int mt = 0; mt < 4; mt++)
        #pragma unroll
        for (int nt = 0; nt < 4; nt++)
            #pragma unroll
            for (int e = 0; e < 4; e++) acc[mt][nt][e] = 0.f;

    int NC = K >> 5;

    auto load_chunk = [&](int c) {
        int buf = c & 1;
        int k0 = c << 5;
        #pragma unroll
        for (int i = 0; i < 2; i++) {
            int u = tid*2 + i;
            int r = u >> 2;
            int q = u & 3;
            uint32_t doff = (uint32_t)(r*APITCH + q*8) * 2;
            int gr = m0 + r;
            int ok = (gr < M) ? 16 : 0;
            if (gr >= M) gr = 0;
            cpasync16(aB[buf] + doff, A  + (size_t)gr*lda + k0 + q*8, ok);
            cpasync16(bB[buf] + doff, Bt + (size_t)(n0 + r)*ldb + k0 + q*8, 16);
        }
        cp_commit();
    };

    load_chunk(0);

    int rA = lane & 15;
    int cA = (lane >> 4) * 8;

    for (int c = 0; c < NC; c++) {
        if (c + 1 < NC) { load_chunk(c + 1); cp_wait<1>(); }
        else            { cp_wait<0>(); }
        __syncthreads();

        int buf = c & 1;
        uint32_t ab = aB[buf], bb = bB[buf];
        #pragma unroll
        for (int kk = 0; kk < 32; kk += 16) {
            uint32_t af[4][4], bf[2][4];
            #pragma unroll
            for (int mt = 0; mt < 4; mt++)
                ldmx4(af[mt], ab + (uint32_t)((wm*64 + mt*16 + rA)*APITCH + kk + cA)*2);
            #pragma unroll
            for (int p = 0; p < 2; p++)
                ldmx4(bf[p], bb + (uint32_t)((wn*32 + p*16 + rA)*APITCH + kk + cA)*2);
            #pragma unroll
            for (int mt = 0; mt < 4; mt++)
                #pragma unroll
                for (int nt = 0; nt < 4; nt++)
                    mma_f16(acc[mt][nt], af[mt], bf[nt>>1][nt&1], bf[nt>>1][(nt&1)+2]);
        }
        __syncthreads();
    }

    float oscale = (EPI == 0 && z == 0) ? 0.125f : 1.0f;
    int g  = lane >> 2;
    int t4 = lane & 3;
    #pragma unroll
    for (int mt = 0; mt < 4; mt++) {
        #pragma unroll
        for (int h = 0; h < 2; h++) {
            int row = m0 + wm*64 + mt*16 + g + h*8;
            if (row < M) {
                #pragma unroll
                for (int nt = 0; nt < 4; nt++) {
                    int col = n0 + wn*32 + nt*8 + 2*t4;
                    float x = acc[mt][nt][h*2 + 0];
                    float y = acc[mt][nt][h*2 + 1];
                    if (EPI != 3) { x += bias[col]; y += bias[col + 1]; }
                    if (EPI == 0) { x *= oscale; y *= oscale; }
                    if (EPI == 1) {
                        x = (x >= 0.f) ? x : 0.01f*x;
                        y = (y >= 0.f) ? y : 0.01f*y;
                    }
                    if (OUT16) {
                        __half2 o = __floats2half2_rn(x, y);
                        *(__half2*)((__half*)Cv + (size_t)row*N + col) = o;
                    } else {
                        float2 o; o.x = x; o.y = y;
                        *(float2*)((float*)Cv + (size_t)row*N + col) = o;
                    }
                }
            }
        }
    }
}

// ---------------- HMMA flash attention, split-K x2 (round-11 proven) -------
// Q pre-scaled by 0.125 in QKV epilogue; pb already carries pos*inv + mask.
#define BQ 128
#define BK 64
#define QP 72
#define NKT 33
#define ATTN_SMEM ((128*QP + 4*64*QP) * 2)

__device__ __forceinline__ int expand_map(int i) {
    return (i < 8) ? i : 8 + ((i - 8) >> 2);
}

__global__ void __launch_bounds__(256, 2) attn_kernel(
    const __half* __restrict__ Q, const __half* __restrict__ K,
    const __half* __restrict__ V)
{
    extern __shared__ __half sm16[];
    __half* sQ = sm16;
    __half* sK = sQ + 128*QP;
    __half* sV = sK + 2*64*QP;

    int h  = blockIdx.y;
    int q0 = blockIdx.x * BQ;
    int split = blockIdx.z;
    int ntiles = (NKT + 1 - split) >> 1;
    int tid = threadIdx.x;
    int lane = tid & 31, wid = tid >> 5;
    int g = lane >> 2, t4 = lane & 3;
    int rA = lane & 15, cA = (lane >> 4) * 8;

    uint32_t sQu = (uint32_t)__cvta_generic_to_shared(sQ);
    uint32_t sKu = (uint32_t)__cvta_generic_to_shared(sK);
    uint32_t sVu = (uint32_t)__cvta_generic_to_shared(sV);

    #pragma unroll
    for (int i = 0; i < 4; i++) {
        int u = tid*4 + i;
        int r = u >> 3, q = u & 7;
        int qi = q0 + r;
        int ok = (qi < TT) ? 16 : 0;
        if (qi >= TT) qi = 0;
        cpasync16(sQu + (uint32_t)(r*QP + q*8)*2, Q + (size_t)qi*HIDD + h*ADIM + q*8, ok);
    }
    cp_commit();

    auto loadKV = [&](int c) {
        int b = c & 1;
        int k0 = (split + 2*c) * BK;
        #pragma unroll
        for (int i = 0; i < 2; i++) {
            int u = tid*2 + i;
            int r = u >> 3, q = u & 7;
            int kj = k0 + r;
            int ok = (kj < TT) ? 16 : 0;
            if (kj >= TT) kj = 0;
            uint32_t doff = (uint32_t)(b*64*QP + r*QP + q*8)*2;
            cpasync16(sKu + doff, K + (size_t)kj*HIDD + h*ADIM + q*8, ok);
            cpasync16(sVu + doff, V + (size_t)kj*HIDD + h*ADIM + q*8, ok);
        }
        cp_commit();
    };

    loadKV(0);
    cp_wait<1>();
    __syncthreads();

    uint32_t qf[4][4];
    #pragma unroll
    for (int ks = 0; ks < 4; ks++)
        ldmx4(qf[ks], sQu + (uint32_t)((wid*16 + rA)*QP + ks*16 + cA)*2);

    int qi_g  = q0 + wid*16 + g;
    int qi_g8 = qi_g + 8;
    const float* pb0 = g_PB + ((size_t)h*NTOK + expand_map(qi_g  < TT ? qi_g  : 0))*NTOK;
    const float* pb1 = g_PB + ((size_t)h*NTOK + expand_map(qi_g8 < TT ? qi_g8 : 0))*NTOK;

    float mrun0 = -1e30f, mrun1 = -1e30f;
    float l0 = 0.f, l1 = 0.f;
    float of[8][4];
    #pragma unroll
    for (int nt = 0; nt < 8; nt++)
        #pragma unroll
        for (int e = 0; e < 4; e++) of[nt][e] = 0.f;

    for (int c = 0; c < ntiles; c++) {
        if (c + 1 < ntiles) { loadKV(c + 1); cp_wait<1>(); }
        else                { cp_wait<0>(); }
        __syncthreads();

        int b = c & 1;
        int k0 = (split + 2*c) * BK;
        uint32_t kb = sKu + (uint32_t)(b*64*QP)*2;
        uint32_t vb = sVu + (uint32_t)(b*64*QP)*2;

        float sc[8][4];
        #pragma unroll
        for (int nt = 0; nt < 8; nt++)
            #pragma unroll
            for (int e = 0; e < 4; e++) sc[nt][e] = 0.f;
        #pragma unroll
        for (int ks = 0; ks < 4; ks++) {
            #pragma unroll
            for (int kr = 0; kr < 4; kr++) {
                uint32_t kf[4];
                ldmx4(kf, kb + (uint32_t)((kr*16 + rA)*QP + ks*16 + cA)*2);
                mma_f16(sc[2*kr],     qf[ks], kf[0], kf[2]);
                mma_f16(sc[2*kr + 1], qf[ks], kf[1], kf[3]);
            }
        }

        // bias + mask (Q already scaled by 0.125)
        #pragma unroll
        for (int nt = 0; nt < 8; nt++) {
            int kj0 = k0 + nt*8 + 2*t4;
            if (kj0 < TT) {
                int oj = expand_map(kj0);
                sc[nt][0] += pb0[oj];
                sc[nt][2] += pb1[oj];
            } else { sc[nt][0] = -1e30f; sc[nt][2] = -1e30f; }
            int kj1 = kj0 + 1;
            if (kj1 < TT) {
                int oj = expand_map(kj1);
                sc[nt][1] += pb0[oj];
                sc[nt][3] += pb1[oj];
            } else { sc[nt][1] = -1e30f; sc[nt][3] = -1e30f; }
        }

        float m0 = -1e30f, m1 = -1e30f;
        #pragma unroll
        for (int nt = 0; nt < 8; nt++) {
            m0 = fmaxf(m0, fmaxf(sc[nt][0], sc[nt][1]));
            m1 = fmaxf(m1, fmaxf(sc[nt][2], sc[nt][3]));
        }
        m0 = fmaxf(m0, __shfl_xor_sync(0xffffffffu, m0, 1));
        m0 = fmaxf(m0, __shfl_xor_sync(0xffffffffu, m0, 2));
        m1 = fmaxf(m1, __shfl_xor_sync(0xffffffffu, m1, 1));
        m1 = fmaxf(m1, __shfl_xor_sync(0xffffffffu, m1, 2));
        float mn0 = fmaxf(mrun0, m0), mn1 = fmaxf(mrun1, m1);
        float c0 = __expf(mrun0 - mn0), c1 = __expf(mrun1 - mn1);
        mrun0 = mn0; mrun1 = mn1;

        float ls0 = 0.f, ls1 = 0.f;
        uint32_t pa[4][4];
        #pragma unroll
        for (int nt = 0; nt < 8; nt++) {
            float p0 = __expf(sc[nt][0] - mn0);
            float p1 = __expf(sc[nt][1] - mn0);
            float p2 = __expf(sc[nt][2] - mn1);
            float p3 = __expf(sc[nt][3] - mn1);
            ls0 += p0 + p1; ls1 += p2 + p3;
            uint32_t h01 = h2_as_u32(__floats2half2_rn(p0, p1));
            uint32_t h23 = h2_as_u32(__floats2half2_rn(p2, p3));
            int s = nt >> 1;
            if ((nt & 1) == 0) { pa[s][0] = h01; pa[s][1] = h23; }
            else               { pa[s][2] = h01; pa[s][3] = h23; }
        }
        ls0 += __shfl_xor_sync(0xffffffffu, ls0, 1);
        ls0 += __shfl_xor_sync(0xffffffffu, ls0, 2);
        ls1 += __shfl_xor_sync(0xffffffffu, ls1, 1);
        ls1 += __shfl_xor_sync(0xffffffffu, ls1, 2);
        l0 = l0*c0 + ls0;
        l1 = l1*c1 + ls1;

        #pragma unroll
        for (int nt = 0; nt < 8; nt++) {
            of[nt][0] *= c0; of[nt][1] *= c0;
            of[nt][2] *= c1; of[nt][3] *= c1;
        }

        int vrow = ((lane >> 3) & 1)*8 + (lane & 7);
        int vcol = (lane >> 4)*8;
        #pragma unroll
        for (int s = 0; s < 4; s++) {
            #pragma unroll
            for (int dn = 0; dn < 4; dn++) {
                uint32_t vf[4];
                ldmx4t(vf, vb + (uint32_t)((s*16 + vrow)*QP + dn*16 + vcol)*2);
                mma_f16(of[2*dn],     pa[s], vf[0], vf[1]);
                mma_f16(of[2*dn + 1], pa[s], vf[2], vf[3]);
            }
        }
        __syncthreads();
    }

    #pragma unroll
    for (int nt = 0; nt < 8; nt++) {
        int d = nt*8 + 2*t4;
        if (qi_g < TT) {
            float2 o; o.x = of[nt][0]; o.y = of[nt][1];
            *(float2*)&g_OP[split][(size_t)qi_g*HIDD + h*ADIM + d] = o;
        }
        if (qi_g8 < TT) {
            float2 o; o.x = of[nt][2]; o.y = of[nt][3];
            *(float2*)&g_OP[split][(size_t)qi_g8*HIDD + h*ADIM + d] = o;
        }
    }
    if (t4 == 0) {
        if (qi_g  < TT) { float2 ml; ml.x = mrun0; ml.y = l0; g_ML[split][(size_t)qi_g*NHEAD  + h] = ml; }
        if (qi_g8 < TT) { float2 ml; ml.x = mrun1; ml.y = l1; g_ML[split][(size_t)qi_g8*NHEAD + h] = ml; }
    }
}

// ---------------- combine the two attention splits ----------------
__global__ void __launch_bounds__(256) attn_combine_kernel(__half* __restrict__ O16)
{
    int row = blockIdx.x;
    int t = threadIdx.x;
    #pragma unroll
    for (int p = 0; p < 2; p++) {
        int e = t + p*256;
        int h = e >> 6;
        float2 ml0 = g_ML[0][(size_t)row*NHEAD + h];
        float2 ml1 = g_ML[1][(size_t)row*NHEAD + h];
        float m = fmaxf(ml0.x, ml1.x);
        float w0 = __expf(ml0.x - m), w1 = __expf(ml1.x - m);
        float denom = ml0.y*w0 + ml1.y*w1;
        float o = (g_OP[0][(size_t)row*HIDD + e]*w0 + g_OP[1][(size_t)row*HIDD + e]*w1) / denom;
        O16[(size_t)row*HIDD + e] = __float2half(o);
    }
}

// ---------------- launch ----------------
extern "C" void kernel_launch(void* const* d_in, const int* in_sizes, int n_in,
                              void* d_out, int out_size)
{
    const float* obj   = (const float*)d_in[0];
    const float* st0   = (const float*)d_in[2];
    const int*   rpe_a = (const int*)  d_in[3];
    const int*   rpe_d = (const int*)  d_in[4];
    const float* mask  = (const float*)d_in[5];
    const float* Wpg   = (const float*)d_in[6];
    const float* bpg   = (const float*)d_in[7];
    const float* pgg   = (const float*)d_in[8];
    const float* pgb   = (const float*)d_in[9];
    const float* Wps   = (const float*)d_in[10];
    const float* bps   = (const float*)d_in[11];
    const float* psg   = (const float*)d_in[12];
    const float* psb   = (const float*)d_in[13];
    const float* emb_a = (const float*)d_in[14];
    const float* emb_d = (const float*)d_in[15];
    const float* Wq    = (const float*)d_in[16];
    const float* bq    = (const float*)d_in[17];
    const float* Wk    = (const float*)d_in[18];
    const float* bk    = (const float*)d_in[19];
    const float* Wv    = (const float*)d_in[20];
    const float* bv    = (const float*)d_in[21];
    const float* Wo    = (const float*)d_in[22];
    const float* bo    = (const float*)d_in[23];
    const float* W1    = (const float*)d_in[24];
    const float* b1    = (const float*)d_in[25];
    const float* W2    = (const float*)d_in[26];
    const float* b2    = (const float*)d_in[27];
    const float* ln1g  = (const float*)d_in[28];
    const float* ln1b  = (const float*)d_in[29];
    const float* ln2g  = (const float*)d_in[30];
    const float* ln2b  = (const float*)d_in[31];
    float* out = (float*)d_out;

    float *X, *P;
    __half *X16, *Q16, *K16, *V16, *O16, *H16;
    __half *WtQ, *WtK, *WtV, *WtO, *WtF1, *WtF2;
    cudaGetSymbolAddress((void**)&X,    g_X);
    cudaGetSymbolAddress((void**)&X16,  g_X16);
    cudaGetSymbolAddress((void**)&P,    g_P);
    cudaGetSymbolAddress((void**)&Q16,  g_Q16);
    cudaGetSymbolAddress((void**)&K16,  g_K16);
    cudaGetSymbolAddress((void**)&V16,  g_V16);
    cudaGetSymbolAddress((void**)&O16,  g_O16);
    cudaGetSymbolAddress((void**)&H16,  g_H16);
    cudaGetSymbolAddress((void**)&WtQ,  g_WtQ);
    cudaGetSymbolAddress((void**)&WtK,  g_WtK);
    cudaGetSymbolAddress((void**)&WtV,  g_WtV);
    cudaGetSymbolAddress((void**)&WtO,  g_WtO);
    cudaGetSymbolAddress((void**)&WtF1, g_WtF1);
    cudaGetSymbolAddress((void**)&WtF2, g_WtF2);

    cudaFuncSetAttribute(attn_kernel, cudaFuncAttributeMaxDynamicSharedMemorySize, ATTN_SMEM);

    transpose4_kernel<<<dim3(16,16,24), 256>>>(Wq, Wk, Wv, Wo, WtQ, WtK, WtV, WtO);
    transpose_kernel<<<dim3(64,16,6), 256>>>(W1, WtF1, HIDD, FFD, (long)HIDD*FFD, (long)FFD*HIDD);
    transpose_kernel<<<dim3(16,64,6), 256>>>(W2, WtF2, FFD, HIDD, (long)FFD*HIDD, (long)HIDD*FFD);

    pb_kernel<<<(NTOK*NTOK + 255)/256, 256>>>(rpe_a, rpe_d, mask, emb_a, emb_d);
    embed_kernel<<<TT, 256>>>(obj, st0, Wpg, bpg, pgg, pgb, Wps, bps, psg, psb);

    for (int l = 0; l < 6; l++) {
        const __half* WtQl  = WtQ  + (size_t)l*HIDD*HIDD;
        const __half* WtKl  = WtK  + (size_t)l*HIDD*HIDD;
        const __half* WtVl  = WtV  + (size_t)l*HIDD*HIDD;
        const __half* WtOl  = WtO  + (size_t)l*HIDD*HIDD;
        const __half* WtF1l = WtF1 + (size_t)l*HIDD*FFD;
        const __half* WtF2l = WtF2 + (size_t)l*FFD*HIDD;
        const float* bql = bq + (size_t)l*HIDD;
        const float* bkl = bk + (size_t)l*HIDD;
        const float* bvl = bv + (size_t)l*HIDD;
        const float* bol = bo + (size_t)l*HIDD;
        const float* b1l = b1 + (size_t)l*FFD;
        const float* b2l = b2 + (size_t)l*HIDD;

        // fused QKV -> fp16 (Q pre-scaled by 0.125 in epilogue)
        tgemm_kernel<0, true><<<dim3(4, 17, 3), 256>>>(
            X16, WtQl, WtKl, WtVl, bql, bkl, bvl, Q16, K16, V16,
            TT, HIDD, HIDD, HIDD, HIDD);

        attn_kernel<<<dim3(17, NHEAD, 2), 256, ATTN_SMEM>>>(Q16, K16, V16);
        attn_combine_kernel<<<TT, 256>>>(O16);

        // O-proj split-K x4 -> 4 partials in g_P (272 CTAs, full chip)
        tgemm_kernel<3, false><<<dim3(4, 17, 4), 256>>>(
            O16, WtOl, WtOl, WtOl, nullptr, nullptr, nullptr, P, P, P,
            TT, HIDD, HIDD/4, HIDD, HIDD);
        ln_sum_kernel<4><<<257, 256>>>(P, X, bol, ln1g + l*HIDD, ln1b + l*HIDD, X, X16);

        // FF1 -> H16
        tgemm_kernel<1, true><<<dim3(16, 17, 1), 256>>>(
            X16, WtF1l, WtF1l, WtF1l, b1l, b1l, b1l, H16, H16, H16,
            TT, FFD, HIDD, HIDD, HIDD);

        // FF2 split-K x4 -> 4 partials in g_P
        tgemm_kernel<3, false><<<dim3(4, 17, 4), 256>>>(
            H16, WtF2l, WtF2l, WtF2l, nullptr, nullptr, nullptr, P, P, P,
            TT, HIDD, FFD/4, FFD, FFD);
        ln_sum_kernel<4><<<257, 256>>>(P, X, b2l, ln2g + l*HIDD, ln2b + l*HIDD,
                                       (l == 5) ? out : X, (l == 5) ? nullptr : X16);
    }
}